// round 11
// baseline (speedup 1.0000x reference)
#include <cuda_runtime.h>
#include <cstdint>

#define T_STEPS 512
#define BSZ     64
#define NIN     1024
#define HID     1024
#define NOUT    1024

// recurrence partition
#define NC       8
#define KC       128
#define JT       64
#define RNN_BLOCKS 128
#define SHS      132          // padded smem row stride (floats)

// scratch
__device__ float   g_UH[(size_t)T_STEPS * BSZ * HID];   // U (input contribs)
__device__ float   g_Hhi[BSZ * HID];                    // tf32-hi of current h
__device__ float   g_Hlo[BSZ * HID];                    // tf32-lo of current h
__device__ float   g_part[NC * BSZ * HID];              // recurrence partials
__device__ float   g_part3[NC * BSZ * NOUT];            // fused-GEMM3 partials
__device__ unsigned g_cnt;
__device__ unsigned g_gen;

// ===========================================================================
// common helpers
// ===========================================================================
__device__ __forceinline__ void cp_async16(uint32_t smem_addr, const void* gptr) {
    asm volatile("cp.async.cg.shared.global [%0], [%1], 16;"
                 :: "r"(smem_addr), "l"(gptr));
}
__device__ __forceinline__ uint32_t smem_u32(const void* p) {
    uint32_t a;
    asm("{ .reg .u64 t; cvta.to.shared.u64 t, %1; cvt.u32.u64 %0, t; }"
        : "=r"(a) : "l"(p));
    return a;
}
__device__ __forceinline__ uint32_t f2tf32(float v) {
    uint32_t r;
    asm("cvt.rna.tf32.f32 %0, %1;" : "=r"(r) : "f"(v));
    return r;
}
__device__ __forceinline__ void tf32_split(float x, uint32_t& hi, uint32_t& lo) {
    hi = f2tf32(x);
    lo = f2tf32(x - __uint_as_float(hi));
}
__device__ __forceinline__ void split4(float4 v, float4& hv, float4& lv) {
    uint32_t h, l;
    tf32_split(v.x, h, l); hv.x = __uint_as_float(h); lv.x = __uint_as_float(l);
    tf32_split(v.y, h, l); hv.y = __uint_as_float(h); lv.y = __uint_as_float(l);
    tf32_split(v.z, h, l); hv.z = __uint_as_float(h); lv.z = __uint_as_float(l);
    tf32_split(v.w, h, l); hv.w = __uint_as_float(h); lv.w = __uint_as_float(l);
}
__device__ __forceinline__ void mma_tf32(
    float& d0, float& d1, float& d2, float& d3,
    uint32_t a0, uint32_t a1, uint32_t a2, uint32_t a3,
    uint32_t b0, uint32_t b1)
{
    asm volatile(
        "mma.sync.aligned.m16n8k8.row.col.f32.tf32.tf32.f32 "
        "{%0,%1,%2,%3}, {%4,%5,%6,%7}, {%8,%9}, {%0,%1,%2,%3};"
        : "+f"(d0), "+f"(d1), "+f"(d2), "+f"(d3)
        : "r"(a0), "r"(a1), "r"(a2), "r"(a3), "r"(b0), "r"(b1));
}

// ===========================================================================
// 3xTF32 mma.sync GEMM (R5/R7 version — known good, ~1.07ms) — used for GEMM1
// ===========================================================================
#define BM 128
#define BN 128
#define BK 16
#define SST 20

__global__ __launch_bounds__(256) void gemm_mma_k(
    const float* __restrict__ A, int lda,
    const float* __restrict__ Wm, int ldw,
    const float* __restrict__ bias,
    float* __restrict__ C, int ldc, int K)
{
    __shared__ float As[2][BM * SST];
    __shared__ float Ws[2][BN * SST];

    const int tid = threadIdx.x;
    const int wid = tid >> 5;
    const int lane = tid & 31;
    const int m0 = blockIdx.y * BM;
    const int n0 = blockIdx.x * BN;

    const int warp_m = (wid >> 2) * 64;
    const int warp_n = (wid & 3) * 32;

    const int lrow = tid >> 1;
    const int lc   = (tid & 1) * 8;
    const float* Ag = A  + (size_t)(m0 + lrow) * lda + lc;
    const float* Wg = Wm + (size_t)(n0 + lrow) * ldw + lc;
    const uint32_t sAs = smem_u32(&As[0][0]);
    const uint32_t sWs = smem_u32(&Ws[0][0]);
    const uint32_t soff = (uint32_t)(lrow * SST + lc) * 4u;

    const int NK = K / BK;

    {
        cp_async16(sAs + soff,      Ag);
        cp_async16(sAs + soff + 16, Ag + 4);
        cp_async16(sWs + soff,      Wg);
        cp_async16(sWs + soff + 16, Wg + 4);
        asm volatile("cp.async.commit_group;");
    }

    float acc[4][4][4];
#pragma unroll
    for (int i = 0; i < 4; i++)
#pragma unroll
        for (int j = 0; j < 4; j++)
#pragma unroll
            for (int q = 0; q < 4; q++) acc[i][j][q] = 0.0f;

    const int fr = lane >> 2;
    const int fc = lane & 3;

    for (int it = 0; it < NK; it++) {
        const int buf = it & 1;

        if (it + 1 < NK) {
            const uint32_t dst = (it + 1) & 1;
            const float* Ap = Ag + (size_t)(it + 1) * BK;
            const float* Wp = Wg + (size_t)(it + 1) * BK;
            cp_async16(sAs + dst * (BM * SST * 4) + soff,      Ap);
            cp_async16(sAs + dst * (BM * SST * 4) + soff + 16, Ap + 4);
            cp_async16(sWs + dst * (BN * SST * 4) + soff,      Wp);
            cp_async16(sWs + dst * (BN * SST * 4) + soff + 16, Wp + 4);
            asm volatile("cp.async.commit_group;");
            asm volatile("cp.async.wait_group 1;");
        } else {
            asm volatile("cp.async.wait_group 0;");
        }
        __syncthreads();

        const float* Ab = &As[buf][0];
        const float* Wb = &Ws[buf][0];

#pragma unroll
        for (int k8 = 0; k8 < 2; k8++) {
            const int kb = k8 * 8;

            uint32_t bh[4][2], bl[4][2];
#pragma unroll
            for (int j = 0; j < 4; j++) {
                const int nb = warp_n + j * 8;
                float b0 = Wb[(nb + fr) * SST + kb + fc];
                float b1 = Wb[(nb + fr) * SST + kb + fc + 4];
                tf32_split(b0, bh[j][0], bl[j][0]);
                tf32_split(b1, bh[j][1], bl[j][1]);
            }

#pragma unroll
            for (int i = 0; i < 4; i++) {
                const int mb = warp_m + i * 16;
                float a0 = Ab[(mb + fr)     * SST + kb + fc];
                float a1 = Ab[(mb + fr + 8) * SST + kb + fc];
                float a2 = Ab[(mb + fr)     * SST + kb + fc + 4];
                float a3 = Ab[(mb + fr + 8) * SST + kb + fc + 4];
                uint32_t ah[4], al[4];
                tf32_split(a0, ah[0], al[0]);
                tf32_split(a1, ah[1], al[1]);
                tf32_split(a2, ah[2], al[2]);
                tf32_split(a3, ah[3], al[3]);

#pragma unroll
                for (int j = 0; j < 4; j++) {
                    mma_tf32(acc[i][j][0], acc[i][j][1], acc[i][j][2], acc[i][j][3],
                             ah[0], ah[1], ah[2], ah[3], bh[j][0], bh[j][1]);
                    mma_tf32(acc[i][j][0], acc[i][j][1], acc[i][j][2], acc[i][j][3],
                             ah[0], ah[1], ah[2], ah[3], bl[j][0], bl[j][1]);
                    mma_tf32(acc[i][j][0], acc[i][j][1], acc[i][j][2], acc[i][j][3],
                             al[0], al[1], al[2], al[3], bh[j][0], bh[j][1]);
                }
            }
        }
        __syncthreads();
    }

#pragma unroll
    for (int j = 0; j < 4; j++) {
        const int ncol = n0 + warp_n + j * 8 + fc * 2;
        const float2 bv = *reinterpret_cast<const float2*>(&bias[ncol]);
#pragma unroll
        for (int i = 0; i < 4; i++) {
            const int r0 = m0 + warp_m + i * 16 + fr;
            float2 v0, v1;
            v0.x = acc[i][j][0] + bv.x; v0.y = acc[i][j][1] + bv.y;
            v1.x = acc[i][j][2] + bv.x; v1.y = acc[i][j][3] + bv.y;
            *reinterpret_cast<float2*>(&C[(size_t)r0 * ldc + ncol])       = v0;
            *reinterpret_cast<float2*>(&C[(size_t)(r0 + 8) * ldc + ncol]) = v1;
        }
    }
}

// ===========================================================================
// R7 atomic grid barrier (measured best)
// ===========================================================================
__device__ __forceinline__ void grid_barrier_fast()
{
    __syncthreads();
    if (threadIdx.x == 0) {
        unsigned gen;
        asm volatile("ld.acquire.gpu.global.u32 %0, [%1];"
                     : "=r"(gen) : "l"(&g_gen));
        unsigned old;
        asm volatile("atom.acq_rel.gpu.global.add.u32 %0, [%1], 1;"
                     : "=r"(old) : "l"(&g_cnt));
        if (old == gridDim.x - 1) {
            asm volatile("st.relaxed.gpu.global.u32 [%0], 0;"
                         :: "l"(&g_cnt));
            asm volatile("red.release.gpu.global.add.u32 [%0], 1;"
                         :: "l"(&g_gen));
        } else {
            unsigned cur;
            do {
                asm volatile("ld.acquire.gpu.global.u32 %0, [%1];"
                             : "=r"(cur) : "l"(&g_gen));
            } while (cur == gen);
        }
    }
    __syncthreads();
}

// ===========================================================================
// Persistent recurrence + FUSED output GEMM.
// Per step t: stage h(t-1) chunk; Phase A (recurrence partials, t);
// Phase A3 (out(t-1) partials from same staged h, vs smem Wo slab);
// B1; Phase B: reduce h(t) + reduce out(t-1); B2.
// Epilogue handles out(511).
// ===========================================================================
__global__ __launch_bounds__(256) void rnn_scan_k(
    const float* __restrict__ h0, const float* __restrict__ Wi2h,
    const float* __restrict__ Wh2o, const float* __restrict__ b_h2o,
    float* __restrict__ out)
{
    extern __shared__ float sm[];
    float* sh_hi = sm;                     // [64][SHS]
    float* sh_lo = sm + 64 * SHS;          // [64][SHS]
    float* wo_hi = sm + 2 * 64 * SHS;      // [64][SHS] Wo slab hi
    float* wo_lo = sm + 3 * 64 * SHS;      // [64][SHS] Wo slab lo

    const int tid = threadIdx.x;
    const int bid = blockIdx.x;
    const int wid = tid >> 5;
    const int lane = tid & 31;
    const int c   = bid >> 4;
    const int jt  = bid & 15;
    const int j0  = jt * JT;
    const int k0  = c * KC;

    const int mh = wid >> 2;
    const int nw = wid & 3;
    const int fr = lane >> 2;
    const int fc = lane & 3;

    // preload W_h fragments (loop-invariant, registers)
    uint32_t Wh[2][16][2], Wl[2][16][2];
#pragma unroll
    for (int nj = 0; nj < 2; nj++) {
        const int n = j0 + nw * 16 + nj * 8 + fr;
        const float* wr = &Wi2h[(size_t)n * (NIN + HID) + NIN + k0];
#pragma unroll
        for (int ks = 0; ks < 16; ks++) {
            tf32_split(wr[ks * 8 + fc],     Wh[nj][ks][0], Wl[nj][ks][0]);
            tf32_split(wr[ks * 8 + fc + 4], Wh[nj][ks][1], Wl[nj][ks][1]);
        }
    }

    // preload Wo slab into smem (loop-invariant): rows = out cols [j0,+64),
    // cols = k chunk [k0,+128), split hi/lo
    for (int idx = tid; idx < JT * KC; idx += 256) {
        const int n = idx >> 7;            // 0..63
        const int k = idx & (KC - 1);
        uint32_t h, l;
        tf32_split(Wh2o[(size_t)(j0 + n) * HID + k0 + k], h, l);
        wo_hi[n * SHS + k] = __uint_as_float(h);
        wo_lo[n * SHS + k] = __uint_as_float(l);
    }

    // Phase B ownership: 512 elements, 2 consecutive per thread
    const int pb_flat = bid * 512 + 2 * tid;
    const int pb_b = pb_flat >> 10;
    const int pb_j = pb_flat & (HID - 1);
    const float2 ob = *reinterpret_cast<const float2*>(&b_h2o[pb_j]);

    for (int t = 0; t < T_STEPS; t++) {
        // --- stage h(t-1) chunk into smem (split form) ---
        if (t == 0) {
#pragma unroll
            for (int p = 0; p < 8; p++) {
                const int idx4 = tid + p * 256;
                const int b = idx4 >> 5;
                const int kg = (idx4 & 31) * 4;
                float4 v = *reinterpret_cast<const float4*>(&h0[b * HID + k0 + kg]);
                float4 hv, lv;
                split4(v, hv, lv);
                *reinterpret_cast<float4*>(&sh_hi[b * SHS + kg]) = hv;
                *reinterpret_cast<float4*>(&sh_lo[b * SHS + kg]) = lv;
            }
        } else {
#pragma unroll
            for (int p = 0; p < 8; p++) {
                const int idx4 = tid + p * 256;
                const int b = idx4 >> 5;
                const int kg = (idx4 & 31) * 4;
                const int goff = b * HID + k0 + kg;
                float4 hv = __ldcg(reinterpret_cast<const float4*>(&g_Hhi[goff]));
                float4 lv = __ldcg(reinterpret_cast<const float4*>(&g_Hlo[goff]));
                *reinterpret_cast<float4*>(&sh_hi[b * SHS + kg]) = hv;
                *reinterpret_cast<float4*>(&sh_lo[b * SHS + kg]) = lv;
            }
        }
        __syncthreads();

        // --- Phase A: recurrence partials (3xTF32, W frags in regs) ---
        {
            float acc[2][2][4];
#pragma unroll
            for (int mi = 0; mi < 2; mi++)
#pragma unroll
                for (int nj = 0; nj < 2; nj++)
#pragma unroll
                    for (int q = 0; q < 4; q++) acc[mi][nj][q] = 0.0f;

#pragma unroll
            for (int ks = 0; ks < 16; ks++) {
                const int kk = ks * 8 + fc;
                uint32_t ahi[2][4], alo[2][4];
#pragma unroll
                for (int mi = 0; mi < 2; mi++) {
                    const int r0 = (mh * 32 + mi * 16 + fr) * SHS;
                    const int r8 = r0 + 8 * SHS;
                    ahi[mi][0] = __float_as_uint(sh_hi[r0 + kk]);
                    ahi[mi][1] = __float_as_uint(sh_hi[r8 + kk]);
                    ahi[mi][2] = __float_as_uint(sh_hi[r0 + kk + 4]);
                    ahi[mi][3] = __float_as_uint(sh_hi[r8 + kk + 4]);
                    alo[mi][0] = __float_as_uint(sh_lo[r0 + kk]);
                    alo[mi][1] = __float_as_uint(sh_lo[r8 + kk]);
                    alo[mi][2] = __float_as_uint(sh_lo[r0 + kk + 4]);
                    alo[mi][3] = __float_as_uint(sh_lo[r8 + kk + 4]);
                }
#pragma unroll
                for (int mi = 0; mi < 2; mi++)
#pragma unroll
                    for (int nj = 0; nj < 2; nj++) {
                        mma_tf32(acc[mi][nj][0], acc[mi][nj][1], acc[mi][nj][2], acc[mi][nj][3],
                                 ahi[mi][0], ahi[mi][1], ahi[mi][2], ahi[mi][3],
                                 Wh[nj][ks][0], Wh[nj][ks][1]);
                        mma_tf32(acc[mi][nj][0], acc[mi][nj][1], acc[mi][nj][2], acc[mi][nj][3],
                                 ahi[mi][0], ahi[mi][1], ahi[mi][2], ahi[mi][3],
                                 Wl[nj][ks][0], Wl[nj][ks][1]);
                        mma_tf32(acc[mi][nj][0], acc[mi][nj][1], acc[mi][nj][2], acc[mi][nj][3],
                                 alo[mi][0], alo[mi][1], alo[mi][2], alo[mi][3],
                                 Wh[nj][ks][0], Wh[nj][ks][1]);
                    }
            }

#pragma unroll
            for (int mi = 0; mi < 2; mi++) {
                const int b0 = mh * 32 + mi * 16 + fr;
#pragma unroll
                for (int nj = 0; nj < 2; nj++) {
                    const int n = j0 + nw * 16 + nj * 8 + fc * 2;
                    float2 v0, v1;
                    v0.x = acc[mi][nj][0]; v0.y = acc[mi][nj][1];
                    v1.x = acc[mi][nj][2]; v1.y = acc[mi][nj][3];
                    __stcg(reinterpret_cast<float2*>(
                        &g_part[(size_t)(c * BSZ + b0) * HID + n]), v0);
                    __stcg(reinterpret_cast<float2*>(
                        &g_part[(size_t)(c * BSZ + b0 + 8) * HID + n]), v1);
                }
            }
        }

        // --- Phase A3: fused output-GEMM partials for out(t-1) (skip t=0) ---
        if (t > 0) {
            float acc[2][2][4];
#pragma unroll
            for (int mi = 0; mi < 2; mi++)
#pragma unroll
                for (int nj = 0; nj < 2; nj++)
#pragma unroll
                    for (int q = 0; q < 4; q++) acc[mi][nj][q] = 0.0f;

#pragma unroll
            for (int ks = 0; ks < 16; ks++) {
                const int kk = ks * 8 + fc;
                uint32_t ahi[2][4], alo[2][4], bh[2][2], bl[2][2];
#pragma unroll
                for (int mi = 0; mi < 2; mi++) {
                    const int r0 = (mh * 32 + mi * 16 + fr) * SHS;
                    const int r8 = r0 + 8 * SHS;
                    ahi[mi][0] = __float_as_uint(sh_hi[r0 + kk]);
                    ahi[mi][1] = __float_as_uint(sh_hi[r8 + kk]);
                    ahi[mi][2] = __float_as_uint(sh_hi[r0 + kk + 4]);
                    ahi[mi][3] = __float_as_uint(sh_hi[r8 + kk + 4]);
                    alo[mi][0] = __float_as_uint(sh_lo[r0 + kk]);
                    alo[mi][1] = __float_as_uint(sh_lo[r8 + kk]);
                    alo[mi][2] = __float_as_uint(sh_lo[r0 + kk + 4]);
                    alo[mi][3] = __float_as_uint(sh_lo[r8 + kk + 4]);
                }
#pragma unroll
                for (int nj = 0; nj < 2; nj++) {
                    const int nr = (nw * 16 + nj * 8 + fr) * SHS + kk;
                    bh[nj][0] = __float_as_uint(wo_hi[nr]);
                    bh[nj][1] = __float_as_uint(wo_hi[nr + 4]);
                    bl[nj][0] = __float_as_uint(wo_lo[nr]);
                    bl[nj][1] = __float_as_uint(wo_lo[nr + 4]);
                }
#pragma unroll
                for (int mi = 0; mi < 2; mi++)
#pragma unroll
                    for (int nj = 0; nj < 2; nj++) {
                        mma_tf32(acc[mi][nj][0], acc[mi][nj][1], acc[mi][nj][2], acc[mi][nj][3],
                                 ahi[mi][0], ahi[mi][1], ahi[mi][2], ahi[mi][3],
                                 bh[nj][0], bh[nj][1]);
                        mma_tf32(acc[mi][nj][0], acc[mi][nj][1], acc[mi][nj][2], acc[mi][nj][3],
                                 ahi[mi][0], ahi[mi][1], ahi[mi][2], ahi[mi][3],
                                 bl[nj][0], bl[nj][1]);
                        mma_tf32(acc[mi][nj][0], acc[mi][nj][1], acc[mi][nj][2], acc[mi][nj][3],
                                 alo[mi][0], alo[mi][1], alo[mi][2], alo[mi][3],
                                 bh[nj][0], bh[nj][1]);
                    }
            }

#pragma unroll
            for (int mi = 0; mi < 2; mi++) {
                const int b0 = mh * 32 + mi * 16 + fr;
#pragma unroll
                for (int nj = 0; nj < 2; nj++) {
                    const int n = j0 + nw * 16 + nj * 8 + fc * 2;
                    float2 v0, v1;
                    v0.x = acc[mi][nj][0]; v0.y = acc[mi][nj][1];
                    v1.x = acc[mi][nj][2]; v1.y = acc[mi][nj][3];
                    __stcg(reinterpret_cast<float2*>(
                        &g_part3[(size_t)(c * BSZ + b0) * NOUT + n]), v0);
                    __stcg(reinterpret_cast<float2*>(
                        &g_part3[(size_t)(c * BSZ + b0 + 8) * NOUT + n]), v1);
                }
            }
        }

        // prefetch U (float2) before the barrier
        const size_t u0 = ((size_t)t * BSZ + pb_b) * HID + pb_j;
        float2 uv = __ldcg(reinterpret_cast<const float2*>(&g_UH[u0]));

        grid_barrier_fast();

        // --- Phase B: reduce h(t); reduce out(t-1) ---
        {
            float v0 = uv.x, v1 = uv.y;
#pragma unroll
            for (int cc = 0; cc < NC; cc++) {
                float2 p = __ldcg(reinterpret_cast<const float2*>(
                    &g_part[(size_t)(cc * BSZ + pb_b) * HID + pb_j]));
                v0 += p.x;
                v1 += p.y;
            }
            v0 = tanhf(v0);
            v1 = tanhf(v1);
            uint32_t h0b, l0b, h1b, l1b;
            tf32_split(v0, h0b, l0b);
            tf32_split(v1, h1b, l1b);
            float2 hv, lv;
            hv.x = __uint_as_float(h0b); hv.y = __uint_as_float(h1b);
            lv.x = __uint_as_float(l0b); lv.y = __uint_as_float(l1b);
            __stcg(reinterpret_cast<float2*>(&g_Hhi[pb_flat]), hv);
            __stcg(reinterpret_cast<float2*>(&g_Hlo[pb_flat]), lv);
        }
        if (t > 0) {
            float o0 = ob.x, o1 = ob.y;
#pragma unroll
            for (int cc = 0; cc < NC; cc++) {
                float2 p = __ldcg(reinterpret_cast<const float2*>(
                    &g_part3[(size_t)(cc * BSZ + pb_b) * NOUT + pb_j]));
                o0 += p.x;
                o1 += p.y;
            }
            float2 ov; ov.x = o0; ov.y = o1;
            *reinterpret_cast<float2*>(
                &out[((size_t)(t - 1) * BSZ + pb_b) * NOUT + pb_j]) = ov;
        }

        grid_barrier_fast();
    }

    // --- Epilogue: out(511) ---
    {
        // stage h(511) chunk
#pragma unroll
        for (int p = 0; p < 8; p++) {
            const int idx4 = tid + p * 256;
            const int b = idx4 >> 5;
            const int kg = (idx4 & 31) * 4;
            const int goff = b * HID + k0 + kg;
            float4 hv = __ldcg(reinterpret_cast<const float4*>(&g_Hhi[goff]));
            float4 lv = __ldcg(reinterpret_cast<const float4*>(&g_Hlo[goff]));
            *reinterpret_cast<float4*>(&sh_hi[b * SHS + kg]) = hv;
            *reinterpret_cast<float4*>(&sh_lo[b * SHS + kg]) = lv;
        }
        __syncthreads();

        float acc[2][2][4];
#pragma unroll
        for (int mi = 0; mi < 2; mi++)
#pragma unroll
            for (int nj = 0; nj < 2; nj++)
#pragma unroll
                for (int q = 0; q < 4; q++) acc[mi][nj][q] = 0.0f;

#pragma unroll
        for (int ks = 0; ks < 16; ks++) {
            const int kk = ks * 8 + fc;
            uint32_t ahi[2][4], alo[2][4], bh[2][2], bl[2][2];
#pragma unroll
            for (int mi = 0; mi < 2; mi++) {
                const int r0 = (mh * 32 + mi * 16 + fr) * SHS;
                const int r8 = r0 + 8 * SHS;
                ahi[mi][0] = __float_as_uint(sh_hi[r0 + kk]);
                ahi[mi][1] = __float_as_uint(sh_hi[r8 + kk]);
                ahi[mi][2] = __float_as_uint(sh_hi[r0 + kk + 4]);
                ahi[mi][3] = __float_as_uint(sh_hi[r8 + kk + 4]);
                alo[mi][0] = __float_as_uint(sh_lo[r0 + kk]);
                alo[mi][1] = __float_as_uint(sh_lo[r8 + kk]);
                alo[mi][2] = __float_as_uint(sh_lo[r0 + kk + 4]);
                alo[mi][3] = __float_as_uint(sh_lo[r8 + kk + 4]);
            }
#pragma unroll
            for (int nj = 0; nj < 2; nj++) {
                const int nr = (nw * 16 + nj * 8 + fr) * SHS + kk;
                bh[nj][0] = __float_as_uint(wo_hi[nr]);
                bh[nj][1] = __float_as_uint(wo_hi[nr + 4]);
                bl[nj][0] = __float_as_uint(wo_lo[nr]);
                bl[nj][1] = __float_as_uint(wo_lo[nr + 4]);
            }
#pragma unroll
            for (int mi = 0; mi < 2; mi++)
#pragma unroll
                for (int nj = 0; nj < 2; nj++) {
                    mma_tf32(acc[mi][nj][0], acc[mi][nj][1], acc[mi][nj][2], acc[mi][nj][3],
                             ahi[mi][0], ahi[mi][1], ahi[mi][2], ahi[mi][3],
                             bh[nj][0], bh[nj][1]);
                    mma_tf32(acc[mi][nj][0], acc[mi][nj][1], acc[mi][nj][2], acc[mi][nj][3],
                             ahi[mi][0], ahi[mi][1], ahi[mi][2], ahi[mi][3],
                             bl[nj][0], bl[nj][1]);
                    mma_tf32(acc[mi][nj][0], acc[mi][nj][1], acc[mi][nj][2], acc[mi][nj][3],
                             alo[mi][0], alo[mi][1], alo[mi][2], alo[mi][3],
                             bh[nj][0], bh[nj][1]);
                }
        }

#pragma unroll
        for (int mi = 0; mi < 2; mi++) {
            const int b0 = mh * 32 + mi * 16 + fr;
#pragma unroll
            for (int nj = 0; nj < 2; nj++) {
                const int n = j0 + nw * 16 + nj * 8 + fc * 2;
                float2 v0, v1;
                v0.x = acc[mi][nj][0]; v0.y = acc[mi][nj][1];
                v1.x = acc[mi][nj][2]; v1.y = acc[mi][nj][3];
                __stcg(reinterpret_cast<float2*>(
                    &g_part3[(size_t)(c * BSZ + b0) * NOUT + n]), v0);
                __stcg(reinterpret_cast<float2*>(
                    &g_part3[(size_t)(c * BSZ + b0 + 8) * NOUT + n]), v1);
            }
        }

        grid_barrier_fast();

        float o0 = ob.x, o1 = ob.y;
#pragma unroll
        for (int cc = 0; cc < NC; cc++) {
            float2 p = __ldcg(reinterpret_cast<const float2*>(
                &g_part3[(size_t)(cc * BSZ + pb_b) * NOUT + pb_j]));
            o0 += p.x;
            o1 += p.y;
        }
        float2 ov; ov.x = o0; ov.y = o1;
        *reinterpret_cast<float2*>(
            &out[((size_t)(T_STEPS - 1) * BSZ + pb_b) * NOUT + pb_j]) = ov;
    }
}

// ===========================================================================
extern "C" void kernel_launch(void* const* d_in, const int* in_sizes, int n_in,
                              void* d_out, int out_size)
{
    (void)in_sizes; (void)n_in; (void)out_size;
    const float* x     = (const float*)d_in[0];
    const float* h0    = (const float*)d_in[1];
    const float* W_i2h = (const float*)d_in[2];
    const float* b_i2h = (const float*)d_in[3];
    const float* W_h2o = (const float*)d_in[4];
    const float* b_h2o = (const float*)d_in[5];
    float* out = (float*)d_out;

    float* uh = nullptr;
    cudaGetSymbolAddress((void**)&uh, g_UH);

    // 1) U = X @ Wx^T + b_i2h
    dim3 g1(HID / BN, (T_STEPS * BSZ) / BM);
    gemm_mma_k<<<g1, 256>>>(x, NIN, W_i2h, NIN + HID, b_i2h, uh, HID, NIN);

    // 2) sequential recurrence + fused output GEMM
    int smem = 4 * 64 * SHS * (int)sizeof(float);   // ~135 KB
    cudaFuncSetAttribute(rnn_scan_k, cudaFuncAttributeMaxDynamicSharedMemorySize, smem);
    rnn_scan_k<<<RNN_BLOCKS, 256, smem>>>(h0, W_i2h, W_h2o, b_h2o, out);
}

// round 12
// speedup vs baseline: 1.3526x; 1.3526x over previous
#include <cuda_runtime.h>
#include <cstdint>

#define T_STEPS 512
#define BSZ     64
#define NIN     1024
#define HID     1024
#define NOUT    1024

// recurrence partition
#define NC       8
#define KC       128
#define JT       64
#define RNN_BLOCKS 128
#define SHS      132          // padded smem row stride (floats)

// scratch
__device__ float   g_UH[(size_t)T_STEPS * BSZ * HID];   // U -> h_t (fp32)
__device__ float   g_Hhi[BSZ * HID];                    // tf32-hi of current h
__device__ float   g_Hlo[BSZ * HID];                    // tf32-lo of current h
__device__ float   g_part[NC * BSZ * HID];

// tree barrier state (monotonic within a launch; reset at kernel end)
#define NGRP 16                                  // 16 groups x 8 blocks
__device__ unsigned g_l1[NGRP * 32];             // one counter per 128B line
__device__ unsigned g_l2;
__device__ unsigned g_bcast;
// legacy end-of-kernel barrier (separate state, self-resetting counter)
__device__ unsigned g_cnt2;
__device__ unsigned g_gen2;

// ===========================================================================
// common helpers
// ===========================================================================
__device__ __forceinline__ void cp_async16(uint32_t smem_addr, const void* gptr) {
    asm volatile("cp.async.cg.shared.global [%0], [%1], 16;"
                 :: "r"(smem_addr), "l"(gptr));
}
__device__ __forceinline__ uint32_t smem_u32(const void* p) {
    uint32_t a;
    asm("{ .reg .u64 t; cvta.to.shared.u64 t, %1; cvt.u32.u64 %0, t; }"
        : "=r"(a) : "l"(p));
    return a;
}
__device__ __forceinline__ uint32_t f2tf32(float v) {
    uint32_t r;
    asm("cvt.rna.tf32.f32 %0, %1;" : "=r"(r) : "f"(v));
    return r;
}
__device__ __forceinline__ void tf32_split(float x, uint32_t& hi, uint32_t& lo) {
    hi = f2tf32(x);
    lo = f2tf32(x - __uint_as_float(hi));
}
__device__ __forceinline__ void split4(float4 v, float4& hv, float4& lv) {
    uint32_t h, l;
    tf32_split(v.x, h, l); hv.x = __uint_as_float(h); lv.x = __uint_as_float(l);
    tf32_split(v.y, h, l); hv.y = __uint_as_float(h); lv.y = __uint_as_float(l);
    tf32_split(v.z, h, l); hv.z = __uint_as_float(h); lv.z = __uint_as_float(l);
    tf32_split(v.w, h, l); hv.w = __uint_as_float(h); lv.w = __uint_as_float(l);
}
__device__ __forceinline__ void mma_tf32(
    float& d0, float& d1, float& d2, float& d3,
    uint32_t a0, uint32_t a1, uint32_t a2, uint32_t a3,
    uint32_t b0, uint32_t b1)
{
    asm volatile(
        "mma.sync.aligned.m16n8k8.row.col.f32.tf32.tf32.f32 "
        "{%0,%1,%2,%3}, {%4,%5,%6,%7}, {%8,%9}, {%0,%1,%2,%3};"
        : "+f"(d0), "+f"(d1), "+f"(d2), "+f"(d3)
        : "r"(a0), "r"(a1), "r"(a2), "r"(a3), "r"(b0), "r"(b1));
}

// ===========================================================================
// 3xTF32 mma.sync GEMM (R5/R7 version — known good, ~1.07ms each)
// ===========================================================================
#define BM 128
#define BN 128
#define BK 16
#define SST 20

__global__ __launch_bounds__(256) void gemm_mma_k(
    const float* __restrict__ A, int lda,
    const float* __restrict__ Wm, int ldw,
    const float* __restrict__ bias,
    float* __restrict__ C, int ldc, int K)
{
    __shared__ float As[2][BM * SST];
    __shared__ float Ws[2][BN * SST];

    const int tid = threadIdx.x;
    const int wid = tid >> 5;
    const int lane = tid & 31;
    const int m0 = blockIdx.y * BM;
    const int n0 = blockIdx.x * BN;

    const int warp_m = (wid >> 2) * 64;
    const int warp_n = (wid & 3) * 32;

    const int lrow = tid >> 1;
    const int lc   = (tid & 1) * 8;
    const float* Ag = A  + (size_t)(m0 + lrow) * lda + lc;
    const float* Wg = Wm + (size_t)(n0 + lrow) * ldw + lc;
    const uint32_t sAs = smem_u32(&As[0][0]);
    const uint32_t sWs = smem_u32(&Ws[0][0]);
    const uint32_t soff = (uint32_t)(lrow * SST + lc) * 4u;

    const int NK = K / BK;

    {
        cp_async16(sAs + soff,      Ag);
        cp_async16(sAs + soff + 16, Ag + 4);
        cp_async16(sWs + soff,      Wg);
        cp_async16(sWs + soff + 16, Wg + 4);
        asm volatile("cp.async.commit_group;");
    }

    float acc[4][4][4];
#pragma unroll
    for (int i = 0; i < 4; i++)
#pragma unroll
        for (int j = 0; j < 4; j++)
#pragma unroll
            for (int q = 0; q < 4; q++) acc[i][j][q] = 0.0f;

    const int fr = lane >> 2;
    const int fc = lane & 3;

    for (int it = 0; it < NK; it++) {
        const int buf = it & 1;

        if (it + 1 < NK) {
            const uint32_t dst = (it + 1) & 1;
            const float* Ap = Ag + (size_t)(it + 1) * BK;
            const float* Wp = Wg + (size_t)(it + 1) * BK;
            cp_async16(sAs + dst * (BM * SST * 4) + soff,      Ap);
            cp_async16(sAs + dst * (BM * SST * 4) + soff + 16, Ap + 4);
            cp_async16(sWs + dst * (BN * SST * 4) + soff,      Wp);
            cp_async16(sWs + dst * (BN * SST * 4) + soff + 16, Wp + 4);
            asm volatile("cp.async.commit_group;");
            asm volatile("cp.async.wait_group 1;");
        } else {
            asm volatile("cp.async.wait_group 0;");
        }
        __syncthreads();

        const float* Ab = &As[buf][0];
        const float* Wb = &Ws[buf][0];

#pragma unroll
        for (int k8 = 0; k8 < 2; k8++) {
            const int kb = k8 * 8;

            uint32_t bh[4][2], bl[4][2];
#pragma unroll
            for (int j = 0; j < 4; j++) {
                const int nb = warp_n + j * 8;
                float b0 = Wb[(nb + fr) * SST + kb + fc];
                float b1 = Wb[(nb + fr) * SST + kb + fc + 4];
                tf32_split(b0, bh[j][0], bl[j][0]);
                tf32_split(b1, bh[j][1], bl[j][1]);
            }

#pragma unroll
            for (int i = 0; i < 4; i++) {
                const int mb = warp_m + i * 16;
                float a0 = Ab[(mb + fr)     * SST + kb + fc];
                float a1 = Ab[(mb + fr + 8) * SST + kb + fc];
                float a2 = Ab[(mb + fr)     * SST + kb + fc + 4];
                float a3 = Ab[(mb + fr + 8) * SST + kb + fc + 4];
                uint32_t ah[4], al[4];
                tf32_split(a0, ah[0], al[0]);
                tf32_split(a1, ah[1], al[1]);
                tf32_split(a2, ah[2], al[2]);
                tf32_split(a3, ah[3], al[3]);

#pragma unroll
                for (int j = 0; j < 4; j++) {
                    mma_tf32(acc[i][j][0], acc[i][j][1], acc[i][j][2], acc[i][j][3],
                             ah[0], ah[1], ah[2], ah[3], bh[j][0], bh[j][1]);
                    mma_tf32(acc[i][j][0], acc[i][j][1], acc[i][j][2], acc[i][j][3],
                             ah[0], ah[1], ah[2], ah[3], bl[j][0], bl[j][1]);
                    mma_tf32(acc[i][j][0], acc[i][j][1], acc[i][j][2], acc[i][j][3],
                             al[0], al[1], al[2], al[3], bh[j][0], bh[j][1]);
                }
            }
        }
        __syncthreads();
    }

#pragma unroll
    for (int j = 0; j < 4; j++) {
        const int ncol = n0 + warp_n + j * 8 + fc * 2;
        const float2 bv = *reinterpret_cast<const float2*>(&bias[ncol]);
#pragma unroll
        for (int i = 0; i < 4; i++) {
            const int r0 = m0 + warp_m + i * 16 + fr;
            float2 v0, v1;
            v0.x = acc[i][j][0] + bv.x; v0.y = acc[i][j][1] + bv.y;
            v1.x = acc[i][j][2] + bv.x; v1.y = acc[i][j][3] + bv.y;
            *reinterpret_cast<float2*>(&C[(size_t)r0 * ldc + ncol])       = v0;
            *reinterpret_cast<float2*>(&C[(size_t)(r0 + 8) * ldc + ncol]) = v1;
        }
    }
}

// ===========================================================================
// Tree grid barrier: 16 L1 counters (8 blocks each, distinct lines) ->
// 1 L2 counter (16 arrivals) -> one release store to g_bcast; leaders poll
// the single broadcast word. Monotonic seq; no mid-flight resets.
// Arrival chain ~8x27 (parallel across groups) + 16x27 + release ≈ ~1K cyc
// vs ~3.5K for 128 serialized same-address RMWs.
// ===========================================================================
__device__ __forceinline__ void grid_barrier_tree(unsigned seq)
{
    __syncthreads();
    if (threadIdx.x == 0) {
        const int grp = blockIdx.x >> 3;          // 0..15
        unsigned o1;
        asm volatile("atom.acq_rel.gpu.global.add.u32 %0, [%1], 1;"
                     : "=r"(o1) : "l"(&g_l1[grp * 32]));
        if (o1 == 8u * seq - 1u) {                // group completer
            unsigned o2;
            asm volatile("atom.acq_rel.gpu.global.add.u32 %0, [%1], 1;"
                         : "=r"(o2) : "l"(&g_l2));
            if (o2 == 16u * seq - 1u) {           // global completer
                asm volatile("st.release.gpu.global.u32 [%0], %1;"
                             :: "l"(&g_bcast), "r"(seq));
            }
        }
        unsigned v;
        do {
            asm volatile("ld.acquire.gpu.global.u32 %0, [%1];"
                         : "=r"(v) : "l"(&g_bcast));
        } while (v < seq);
    }
    __syncthreads();
}

// legacy atomic barrier on separate state (used once at scan end for reset)
__device__ __forceinline__ void grid_barrier_atomic()
{
    __syncthreads();
    if (threadIdx.x == 0) {
        unsigned gen;
        asm volatile("ld.acquire.gpu.global.u32 %0, [%1];"
                     : "=r"(gen) : "l"(&g_gen2));
        unsigned old;
        asm volatile("atom.acq_rel.gpu.global.add.u32 %0, [%1], 1;"
                     : "=r"(old) : "l"(&g_cnt2));
        if (old == gridDim.x - 1) {
            asm volatile("st.relaxed.gpu.global.u32 [%0], 0;"
                         :: "l"(&g_cnt2));
            asm volatile("red.release.gpu.global.add.u32 [%0], 1;"
                         :: "l"(&g_gen2));
        } else {
            unsigned cur;
            do {
                asm volatile("ld.acquire.gpu.global.u32 %0, [%1];"
                             : "=r"(cur) : "l"(&g_gen2));
            } while (cur == gen);
        }
    }
    __syncthreads();
}

// ===========================================================================
// Persistent recurrence (exact R7 structure; only the barrier is new)
// ===========================================================================
__global__ __launch_bounds__(256) void rnn_scan_k(
    const float* __restrict__ h0, const float* __restrict__ Wi2h)
{
    extern __shared__ float sm[];
    float* sh_hi = sm;                 // [64][SHS]
    float* sh_lo = sm + 64 * SHS;      // [64][SHS]

    const int tid = threadIdx.x;
    const int bid = blockIdx.x;
    const int wid = tid >> 5;
    const int lane = tid & 31;
    const int c   = bid >> 4;
    const int jt  = bid & 15;
    const int j0  = jt * JT;
    const int k0  = c * KC;

    const int mh = wid >> 2;
    const int nw = wid & 3;
    const int fr = lane >> 2;
    const int fc = lane & 3;

    // preload W fragments (loop-invariant)
    uint32_t Wh[2][16][2], Wl[2][16][2];
#pragma unroll
    for (int nj = 0; nj < 2; nj++) {
        const int n = j0 + nw * 16 + nj * 8 + fr;
        const float* wr = &Wi2h[(size_t)n * (NIN + HID) + NIN + k0];
#pragma unroll
        for (int ks = 0; ks < 16; ks++) {
            tf32_split(wr[ks * 8 + fc],     Wh[nj][ks][0], Wl[nj][ks][0]);
            tf32_split(wr[ks * 8 + fc + 4], Wh[nj][ks][1], Wl[nj][ks][1]);
        }
    }

    // Phase B ownership: 512 elements, 2/thread (R7 strided layout)
    const int pb_i0 = bid * 512 + tid;
    const int pb_i1 = bid * 512 + tid + 256;
    const int pb_b0 = pb_i0 >> 10, pb_j0 = pb_i0 & (HID - 1);
    const int pb_b1 = pb_i1 >> 10, pb_j1 = pb_i1 & (HID - 1);

    for (int t = 0; t < T_STEPS; t++) {
        // --- stage h(t-1) chunk into smem (split form) ---
        if (t == 0) {
#pragma unroll
            for (int p = 0; p < 8; p++) {
                const int idx4 = tid + p * 256;
                const int b = idx4 >> 5;
                const int kg = (idx4 & 31) * 4;
                float4 v = *reinterpret_cast<const float4*>(&h0[b * HID + k0 + kg]);
                float4 hv, lv;
                split4(v, hv, lv);
                *reinterpret_cast<float4*>(&sh_hi[b * SHS + kg]) = hv;
                *reinterpret_cast<float4*>(&sh_lo[b * SHS + kg]) = lv;
            }
        } else {
#pragma unroll
            for (int p = 0; p < 8; p++) {
                const int idx4 = tid + p * 256;
                const int b = idx4 >> 5;
                const int kg = (idx4 & 31) * 4;
                const int goff = b * HID + k0 + kg;
                float4 hv = __ldcg(reinterpret_cast<const float4*>(&g_Hhi[goff]));
                float4 lv = __ldcg(reinterpret_cast<const float4*>(&g_Hlo[goff]));
                *reinterpret_cast<float4*>(&sh_hi[b * SHS + kg]) = hv;
                *reinterpret_cast<float4*>(&sh_lo[b * SHS + kg]) = lv;
            }
        }
        __syncthreads();

        // --- Phase A: 3xTF32 mma over 16 k8 steps ---
        float acc[2][2][4];
#pragma unroll
        for (int mi = 0; mi < 2; mi++)
#pragma unroll
            for (int nj = 0; nj < 2; nj++)
#pragma unroll
                for (int q = 0; q < 4; q++) acc[mi][nj][q] = 0.0f;

#pragma unroll
        for (int ks = 0; ks < 16; ks++) {
            const int kk = ks * 8 + fc;
            uint32_t ahi[2][4], alo[2][4];
#pragma unroll
            for (int mi = 0; mi < 2; mi++) {
                const int r0 = (mh * 32 + mi * 16 + fr) * SHS;
                const int r8 = r0 + 8 * SHS;
                ahi[mi][0] = __float_as_uint(sh_hi[r0 + kk]);
                ahi[mi][1] = __float_as_uint(sh_hi[r8 + kk]);
                ahi[mi][2] = __float_as_uint(sh_hi[r0 + kk + 4]);
                ahi[mi][3] = __float_as_uint(sh_hi[r8 + kk + 4]);
                alo[mi][0] = __float_as_uint(sh_lo[r0 + kk]);
                alo[mi][1] = __float_as_uint(sh_lo[r8 + kk]);
                alo[mi][2] = __float_as_uint(sh_lo[r0 + kk + 4]);
                alo[mi][3] = __float_as_uint(sh_lo[r8 + kk + 4]);
            }
#pragma unroll
            for (int mi = 0; mi < 2; mi++)
#pragma unroll
                for (int nj = 0; nj < 2; nj++) {
                    mma_tf32(acc[mi][nj][0], acc[mi][nj][1], acc[mi][nj][2], acc[mi][nj][3],
                             ahi[mi][0], ahi[mi][1], ahi[mi][2], ahi[mi][3],
                             Wh[nj][ks][0], Wh[nj][ks][1]);
                    mma_tf32(acc[mi][nj][0], acc[mi][nj][1], acc[mi][nj][2], acc[mi][nj][3],
                             ahi[mi][0], ahi[mi][1], ahi[mi][2], ahi[mi][3],
                             Wl[nj][ks][0], Wl[nj][ks][1]);
                    mma_tf32(acc[mi][nj][0], acc[mi][nj][1], acc[mi][nj][2], acc[mi][nj][3],
                             alo[mi][0], alo[mi][1], alo[mi][2], alo[mi][3],
                             Wh[nj][ks][0], Wh[nj][ks][1]);
                }
        }

        // --- write partials (c-frag layout) ---
#pragma unroll
        for (int mi = 0; mi < 2; mi++) {
            const int b0 = mh * 32 + mi * 16 + fr;
#pragma unroll
            for (int nj = 0; nj < 2; nj++) {
                const int n = j0 + nw * 16 + nj * 8 + fc * 2;
                float2 v0, v1;
                v0.x = acc[mi][nj][0]; v0.y = acc[mi][nj][1];
                v1.x = acc[mi][nj][2]; v1.y = acc[mi][nj][3];
                __stcg(reinterpret_cast<float2*>(
                    &g_part[(size_t)(c * BSZ + b0) * HID + n]), v0);
                __stcg(reinterpret_cast<float2*>(
                    &g_part[(size_t)(c * BSZ + b0 + 8) * HID + n]), v1);
            }
        }

        // prefetch U before barrier
        const size_t u0 = ((size_t)t * BSZ + pb_b0) * HID + pb_j0;
        const size_t u1 = ((size_t)t * BSZ + pb_b1) * HID + pb_j1;
        float uv0 = __ldcg(&g_UH[u0]);
        float uv1 = __ldcg(&g_UH[u1]);

        grid_barrier_tree(2u * t + 1u);

        // --- Phase B: reduce + tanh, write h (fp32) and pre-split hi/lo ---
        {
            float v0 = uv0, v1 = uv1;
#pragma unroll
            for (int cc = 0; cc < NC; cc++) {
                v0 += __ldcg(&g_part[(size_t)(cc * BSZ + pb_b0) * HID + pb_j0]);
                v1 += __ldcg(&g_part[(size_t)(cc * BSZ + pb_b1) * HID + pb_j1]);
            }
            v0 = tanhf(v0);
            v1 = tanhf(v1);
            __stcg(&g_UH[u0], v0);
            __stcg(&g_UH[u1], v1);
            uint32_t h0b, l0b, h1b, l1b;
            tf32_split(v0, h0b, l0b);
            tf32_split(v1, h1b, l1b);
            __stcg(&g_Hhi[pb_i0], __uint_as_float(h0b));
            __stcg(&g_Hlo[pb_i0], __uint_as_float(l0b));
            __stcg(&g_Hhi[pb_i1], __uint_as_float(h1b));
            __stcg(&g_Hlo[pb_i1], __uint_as_float(l1b));
        }

        grid_barrier_tree(2u * t + 2u);
    }

    // reset tree-barrier state for the next graph replay, behind a full
    // barrier on separate variables (nobody is polling old state anymore)
    grid_barrier_atomic();
    if (bid == 0) {
        if (tid < NGRP)
            asm volatile("st.relaxed.gpu.global.u32 [%0], 0;"
                         :: "l"(&g_l1[tid * 32]));
        if (tid == 0) {
            asm volatile("st.relaxed.gpu.global.u32 [%0], 0;" :: "l"(&g_l2));
            asm volatile("st.relaxed.gpu.global.u32 [%0], 0;" :: "l"(&g_bcast));
        }
    }
}

// ===========================================================================
extern "C" void kernel_launch(void* const* d_in, const int* in_sizes, int n_in,
                              void* d_out, int out_size)
{
    (void)in_sizes; (void)n_in; (void)out_size;
    const float* x     = (const float*)d_in[0];
    const float* h0    = (const float*)d_in[1];
    const float* W_i2h = (const float*)d_in[2];
    const float* b_i2h = (const float*)d_in[3];
    const float* W_h2o = (const float*)d_in[4];
    const float* b_h2o = (const float*)d_in[5];
    float* out = (float*)d_out;

    float* uh = nullptr;
    cudaGetSymbolAddress((void**)&uh, g_UH);

    // 1) U = X @ Wx^T + b_i2h
    dim3 g1(HID / BN, (T_STEPS * BSZ) / BM);
    gemm_mma_k<<<g1, 256>>>(x, NIN, W_i2h, NIN + HID, b_i2h, uh, HID, NIN);

    // 2) sequential recurrence
    int smem = 2 * 64 * SHS * (int)sizeof(float);
    cudaFuncSetAttribute(rnn_scan_k, cudaFuncAttributeMaxDynamicSharedMemorySize, smem);
    rnn_scan_k<<<RNN_BLOCKS, 256, smem>>>(h0, W_i2h);

    // 3) out = H @ W_h2o^T + b_h2o
    dim3 g3(NOUT / BN, (T_STEPS * BSZ) / BM);
    gemm_mma_k<<<g3, 256>>>(uh, HID, W_h2o, HID, b_h2o, out, NOUT, HID);
}

// round 13
// speedup vs baseline: 1.5996x; 1.1826x over previous
#include <cuda_runtime.h>
#include <cstdint>

#define T_STEPS 512
#define BSZ     64
#define NIN     1024
#define HID     1024
#define NOUT    1024

// recurrence partition
#define NC       8
#define KC       128
#define JT       64
#define RNN_BLOCKS 128
#define SHS      132          // padded smem row stride (floats)

// scratch
__device__ float   g_UH[(size_t)T_STEPS * BSZ * HID];   // U -> h_t (fp32)
__device__ float   g_Hhi[BSZ * HID];                    // tf32-hi of current h
__device__ float   g_Hlo[BSZ * HID];                    // tf32-lo of current h
__device__ float   g_part[NC * BSZ * HID];
__device__ unsigned g_cnt;
__device__ unsigned g_gen;

// ===========================================================================
// common helpers
// ===========================================================================
__device__ __forceinline__ uint32_t smem_u32(const void* p) {
    uint32_t a;
    asm("{ .reg .u64 t; cvta.to.shared.u64 t, %1; cvt.u32.u64 %0, t; }"
        : "=r"(a) : "l"(p));
    return a;
}
__device__ __forceinline__ uint32_t f2tf32(float v) {
    uint32_t r;
    asm("cvt.rna.tf32.f32 %0, %1;" : "=r"(r) : "f"(v));
    return r;
}
__device__ __forceinline__ void tf32_split(float x, uint32_t& hi, uint32_t& lo) {
    hi = f2tf32(x);
    lo = f2tf32(x - __uint_as_float(hi));
}
__device__ __forceinline__ void split4(float4 v, float4& hv, float4& lv) {
    uint32_t h, l;
    tf32_split(v.x, h, l); hv.x = __uint_as_float(h); lv.x = __uint_as_float(l);
    tf32_split(v.y, h, l); hv.y = __uint_as_float(h); lv.y = __uint_as_float(l);
    tf32_split(v.z, h, l); hv.z = __uint_as_float(h); lv.z = __uint_as_float(l);
    tf32_split(v.w, h, l); hv.w = __uint_as_float(h); lv.w = __uint_as_float(l);
}
__device__ __forceinline__ void mma_tf32(
    float& d0, float& d1, float& d2, float& d3,
    uint32_t a0, uint32_t a1, uint32_t a2, uint32_t a3,
    uint32_t b0, uint32_t b1)
{
    asm volatile(
        "mma.sync.aligned.m16n8k8.row.col.f32.tf32.tf32.f32 "
        "{%0,%1,%2,%3}, {%4,%5,%6,%7}, {%8,%9}, {%0,%1,%2,%3};"
        : "+f"(d0), "+f"(d1), "+f"(d2), "+f"(d3)
        : "r"(a0), "r"(a1), "r"(a2), "r"(a3), "r"(b0), "r"(b1));
}
__device__ __forceinline__ void mma_bf16(
    float& d0, float& d1, float& d2, float& d3,
    uint32_t a0, uint32_t a1, uint32_t a2, uint32_t a3,
    uint32_t b0, uint32_t b1)
{
    asm volatile(
        "mma.sync.aligned.m16n8k16.row.col.f32.bf16.bf16.f32 "
        "{%0,%1,%2,%3}, {%4,%5,%6,%7}, {%8,%9}, {%0,%1,%2,%3};"
        : "+f"(d0), "+f"(d1), "+f"(d2), "+f"(d3)
        : "r"(a0), "r"(a1), "r"(a2), "r"(a3), "r"(b0), "r"(b1));
}
// pack two fp32 into bf16x2: low half = f0 (smaller k), high half = f1
__device__ __forceinline__ uint32_t pack_bf16_hi(float f0, float f1) {
    uint32_t r;
    asm("cvt.rn.bf16x2.f32 %0, %1, %2;" : "=r"(r) : "f"(f1), "f"(f0));
    return r;
}
// residual pack: lo = bf16(f - asfloat(hi_bf16))
__device__ __forceinline__ uint32_t pack_bf16_lo(uint32_t hi2, float f0, float f1) {
    float h0 = __uint_as_float(hi2 << 16);
    float h1 = __uint_as_float(hi2 & 0xFFFF0000u);
    uint32_t r;
    asm("cvt.rn.bf16x2.f32 %0, %1, %2;" : "=r"(r) : "f"(f1 - h1), "f"(f0 - h0));
    return r;
}

// ===========================================================================
// bf16x4 GEMM: C[m][n] = sum_k A[m][k]*W[n][k] + bias[n]  (~fp32 accurate)
// CTA 128x128, BK=16 (one m16n8k16 step per iter), 8 warps (2x4),
// warp tile 64x32. Loader converts fp32->packed bf16 hi/lo during STS;
// mainloop is pure LDS.32 + mma (conflict-free via SSTB=12 pair-words).
// Requires M%128==0, N%128==0, K%16==0.
// ===========================================================================
#define BM 128
#define BN 128
#define SSTB 12                    // bf16-pair words per row (8 + 4 pad)
#define BTILE (BM * SSTB)          // 1536 words = 6KB per tile

__global__ __launch_bounds__(256, 2) void gemm_bf16_k(
    const float* __restrict__ A, int lda,
    const float* __restrict__ Wm, int ldw,
    const float* __restrict__ bias,
    float* __restrict__ C, int ldc, int K)
{
    __shared__ uint32_t Ah[2][BTILE], Al[2][BTILE];
    __shared__ uint32_t Wh[2][BTILE], Wl[2][BTILE];   // 48KB total

    const int tid = threadIdx.x;
    const int wid = tid >> 5;
    const int lane = tid & 31;
    const int m0 = blockIdx.y * BM;
    const int n0 = blockIdx.x * BN;

    const int warp_m = (wid >> 2) * 64;
    const int warp_n = (wid & 3) * 32;

    // loader: row = tid>>1 (0..127), 8 floats at col (tid&1)*8 = 4 k-pairs
    const int lrow = tid >> 1;
    const int lc   = (tid & 1) * 8;
    const int pc0  = (tid & 1) * 4;
    const float* Ag = A  + (size_t)(m0 + lrow) * lda + lc;
    const float* Wg = Wm + (size_t)(n0 + lrow) * ldw + lc;
    const int sbase = lrow * SSTB + pc0;

    const int NK = K / 16;

    float4 pa0 = *reinterpret_cast<const float4*>(Ag);
    float4 pa1 = *reinterpret_cast<const float4*>(Ag + 4);
    float4 pw0 = *reinterpret_cast<const float4*>(Wg);
    float4 pw1 = *reinterpret_cast<const float4*>(Wg + 4);

    // store tile 0
    {
        uint32_t h;
        h = pack_bf16_hi(pa0.x, pa0.y); Ah[0][sbase+0] = h; Al[0][sbase+0] = pack_bf16_lo(h, pa0.x, pa0.y);
        h = pack_bf16_hi(pa0.z, pa0.w); Ah[0][sbase+1] = h; Al[0][sbase+1] = pack_bf16_lo(h, pa0.z, pa0.w);
        h = pack_bf16_hi(pa1.x, pa1.y); Ah[0][sbase+2] = h; Al[0][sbase+2] = pack_bf16_lo(h, pa1.x, pa1.y);
        h = pack_bf16_hi(pa1.z, pa1.w); Ah[0][sbase+3] = h; Al[0][sbase+3] = pack_bf16_lo(h, pa1.z, pa1.w);
        h = pack_bf16_hi(pw0.x, pw0.y); Wh[0][sbase+0] = h; Wl[0][sbase+0] = pack_bf16_lo(h, pw0.x, pw0.y);
        h = pack_bf16_hi(pw0.z, pw0.w); Wh[0][sbase+1] = h; Wl[0][sbase+1] = pack_bf16_lo(h, pw0.z, pw0.w);
        h = pack_bf16_hi(pw1.x, pw1.y); Wh[0][sbase+2] = h; Wl[0][sbase+2] = pack_bf16_lo(h, pw1.x, pw1.y);
        h = pack_bf16_hi(pw1.z, pw1.w); Wh[0][sbase+3] = h; Wl[0][sbase+3] = pack_bf16_lo(h, pw1.z, pw1.w);
    }
    __syncthreads();

    float acc[4][4][4];
#pragma unroll
    for (int i = 0; i < 4; i++)
#pragma unroll
        for (int j = 0; j < 4; j++)
#pragma unroll
            for (int q = 0; q < 4; q++) acc[i][j][q] = 0.0f;

    const int fr = lane >> 2;
    const int fc = lane & 3;

    for (int it = 0; it < NK; it++) {
        const int buf = it & 1;

        // prefetch next fp32 tile to registers
        if (it + 1 < NK) {
            const float* Ap = Ag + (size_t)(it + 1) * 16;
            const float* Wp = Wg + (size_t)(it + 1) * 16;
            pa0 = *reinterpret_cast<const float4*>(Ap);
            pa1 = *reinterpret_cast<const float4*>(Ap + 4);
            pw0 = *reinterpret_cast<const float4*>(Wp);
            pw1 = *reinterpret_cast<const float4*>(Wp + 4);
        }

        // compute on current buffer
        {
            uint32_t bh[4][2], bl[4][2];
#pragma unroll
            for (int j = 0; j < 4; j++) {
                const int nb = (warp_n + j * 8 + fr) * SSTB;
                bh[j][0] = Wh[buf][nb + fc];
                bh[j][1] = Wh[buf][nb + fc + 4];
                bl[j][0] = Wl[buf][nb + fc];
                bl[j][1] = Wl[buf][nb + fc + 4];
            }
#pragma unroll
            for (int i = 0; i < 4; i++) {
                const int r0 = (warp_m + i * 16 + fr) * SSTB;
                const int r8 = r0 + 8 * SSTB;
                uint32_t ah[4], al[4];
                ah[0] = Ah[buf][r0 + fc];
                ah[1] = Ah[buf][r8 + fc];
                ah[2] = Ah[buf][r0 + fc + 4];
                ah[3] = Ah[buf][r8 + fc + 4];
                al[0] = Al[buf][r0 + fc];
                al[1] = Al[buf][r8 + fc];
                al[2] = Al[buf][r0 + fc + 4];
                al[3] = Al[buf][r8 + fc + 4];

#pragma unroll
                for (int j = 0; j < 4; j++) {
                    mma_bf16(acc[i][j][0], acc[i][j][1], acc[i][j][2], acc[i][j][3],
                             al[0], al[1], al[2], al[3], bl[j][0], bl[j][1]);
                    mma_bf16(acc[i][j][0], acc[i][j][1], acc[i][j][2], acc[i][j][3],
                             al[0], al[1], al[2], al[3], bh[j][0], bh[j][1]);
                    mma_bf16(acc[i][j][0], acc[i][j][1], acc[i][j][2], acc[i][j][3],
                             ah[0], ah[1], ah[2], ah[3], bl[j][0], bl[j][1]);
                    mma_bf16(acc[i][j][0], acc[i][j][1], acc[i][j][2], acc[i][j][3],
                             ah[0], ah[1], ah[2], ah[3], bh[j][0], bh[j][1]);
                }
            }
        }

        // store prefetched tile into the OTHER buffer (no read/write overlap),
        // then one sync to publish it for the next iteration
        if (it + 1 < NK) {
            const int nb = (it + 1) & 1;
            uint32_t h;
            h = pack_bf16_hi(pa0.x, pa0.y); Ah[nb][sbase+0] = h; Al[nb][sbase+0] = pack_bf16_lo(h, pa0.x, pa0.y);
            h = pack_bf16_hi(pa0.z, pa0.w); Ah[nb][sbase+1] = h; Al[nb][sbase+1] = pack_bf16_lo(h, pa0.z, pa0.w);
            h = pack_bf16_hi(pa1.x, pa1.y); Ah[nb][sbase+2] = h; Al[nb][sbase+2] = pack_bf16_lo(h, pa1.x, pa1.y);
            h = pack_bf16_hi(pa1.z, pa1.w); Ah[nb][sbase+3] = h; Al[nb][sbase+3] = pack_bf16_lo(h, pa1.z, pa1.w);
            h = pack_bf16_hi(pw0.x, pw0.y); Wh[nb][sbase+0] = h; Wl[nb][sbase+0] = pack_bf16_lo(h, pw0.x, pw0.y);
            h = pack_bf16_hi(pw0.z, pw0.w); Wh[nb][sbase+1] = h; Wl[nb][sbase+1] = pack_bf16_lo(h, pw0.z, pw0.w);
            h = pack_bf16_hi(pw1.x, pw1.y); Wh[nb][sbase+2] = h; Wl[nb][sbase+2] = pack_bf16_lo(h, pw1.x, pw1.y);
            h = pack_bf16_hi(pw1.z, pw1.w); Wh[nb][sbase+3] = h; Wl[nb][sbase+3] = pack_bf16_lo(h, pw1.z, pw1.w);
        }
        __syncthreads();
    }

    // epilogue: bias + store (identical acc layout to tf32 version)
#pragma unroll
    for (int j = 0; j < 4; j++) {
        const int ncol = n0 + warp_n + j * 8 + fc * 2;
        const float2 bv = *reinterpret_cast<const float2*>(&bias[ncol]);
#pragma unroll
        for (int i = 0; i < 4; i++) {
            const int r0 = m0 + warp_m + i * 16 + fr;
            float2 v0, v1;
            v0.x = acc[i][j][0] + bv.x; v0.y = acc[i][j][1] + bv.y;
            v1.x = acc[i][j][2] + bv.x; v1.y = acc[i][j][3] + bv.y;
            *reinterpret_cast<float2*>(&C[(size_t)r0 * ldc + ncol])       = v0;
            *reinterpret_cast<float2*>(&C[(size_t)(r0 + 8) * ldc + ncol]) = v1;
        }
    }
}

// ===========================================================================
// R7 flat atomic grid barrier (measured best of all topologies tried)
// ===========================================================================
__device__ __forceinline__ void grid_barrier_fast()
{
    __syncthreads();
    if (threadIdx.x == 0) {
        unsigned gen;
        asm volatile("ld.acquire.gpu.global.u32 %0, [%1];"
                     : "=r"(gen) : "l"(&g_gen));
        unsigned old;
        asm volatile("atom.acq_rel.gpu.global.add.u32 %0, [%1], 1;"
                     : "=r"(old) : "l"(&g_cnt));
        if (old == gridDim.x - 1) {
            asm volatile("st.relaxed.gpu.global.u32 [%0], 0;"
                         :: "l"(&g_cnt));
            asm volatile("red.release.gpu.global.add.u32 [%0], 1;"
                         :: "l"(&g_gen));
        } else {
            unsigned cur;
            do {
                asm volatile("ld.acquire.gpu.global.u32 %0, [%1];"
                             : "=r"(cur) : "l"(&g_gen));
            } while (cur == gen);
        }
    }
    __syncthreads();
}

// ===========================================================================
// Persistent recurrence (R7 exact — tf32x3 Phase A, flat atomic barriers)
// ===========================================================================
__global__ __launch_bounds__(256) void rnn_scan_k(
    const float* __restrict__ h0, const float* __restrict__ Wi2h)
{
    extern __shared__ float sm[];
    float* sh_hi = sm;                 // [64][SHS]
    float* sh_lo = sm + 64 * SHS;      // [64][SHS]

    const int tid = threadIdx.x;
    const int bid = blockIdx.x;
    const int wid = tid >> 5;
    const int lane = tid & 31;
    const int c   = bid >> 4;
    const int jt  = bid & 15;
    const int j0  = jt * JT;
    const int k0  = c * KC;

    const int mh = wid >> 2;
    const int nw = wid & 3;
    const int fr = lane >> 2;
    const int fc = lane & 3;

    // preload W fragments (loop-invariant)
    uint32_t Wh[2][16][2], Wl[2][16][2];
#pragma unroll
    for (int nj = 0; nj < 2; nj++) {
        const int n = j0 + nw * 16 + nj * 8 + fr;
        const float* wr = &Wi2h[(size_t)n * (NIN + HID) + NIN + k0];
#pragma unroll
        for (int ks = 0; ks < 16; ks++) {
            tf32_split(wr[ks * 8 + fc],     Wh[nj][ks][0], Wl[nj][ks][0]);
            tf32_split(wr[ks * 8 + fc + 4], Wh[nj][ks][1], Wl[nj][ks][1]);
        }
    }

    // Phase B ownership: 512 elements, 2/thread
    const int pb_i0 = bid * 512 + tid;
    const int pb_i1 = bid * 512 + tid + 256;
    const int pb_b0 = pb_i0 >> 10, pb_j0 = pb_i0 & (HID - 1);
    const int pb_b1 = pb_i1 >> 10, pb_j1 = pb_i1 & (HID - 1);

    for (int t = 0; t < T_STEPS; t++) {
        // --- stage h(t-1) chunk into smem (split form) ---
        if (t == 0) {
#pragma unroll
            for (int p = 0; p < 8; p++) {
                const int idx4 = tid + p * 256;
                const int b = idx4 >> 5;
                const int kg = (idx4 & 31) * 4;
                float4 v = *reinterpret_cast<const float4*>(&h0[b * HID + k0 + kg]);
                float4 hv, lv;
                split4(v, hv, lv);
                *reinterpret_cast<float4*>(&sh_hi[b * SHS + kg]) = hv;
                *reinterpret_cast<float4*>(&sh_lo[b * SHS + kg]) = lv;
            }
        } else {
#pragma unroll
            for (int p = 0; p < 8; p++) {
                const int idx4 = tid + p * 256;
                const int b = idx4 >> 5;
                const int kg = (idx4 & 31) * 4;
                const int goff = b * HID + k0 + kg;
                float4 hv = __ldcg(reinterpret_cast<const float4*>(&g_Hhi[goff]));
                float4 lv = __ldcg(reinterpret_cast<const float4*>(&g_Hlo[goff]));
                *reinterpret_cast<float4*>(&sh_hi[b * SHS + kg]) = hv;
                *reinterpret_cast<float4*>(&sh_lo[b * SHS + kg]) = lv;
            }
        }
        __syncthreads();

        // --- Phase A: 3xTF32 mma over 16 k8 steps ---
        float acc[2][2][4];
#pragma unroll
        for (int mi = 0; mi < 2; mi++)
#pragma unroll
            for (int nj = 0; nj < 2; nj++)
#pragma unroll
                for (int q = 0; q < 4; q++) acc[mi][nj][q] = 0.0f;

#pragma unroll
        for (int ks = 0; ks < 16; ks++) {
            const int kk = ks * 8 + fc;
            uint32_t ahi[2][4], alo[2][4];
#pragma unroll
            for (int mi = 0; mi < 2; mi++) {
                const int r0 = (mh * 32 + mi * 16 + fr) * SHS;
                const int r8 = r0 + 8 * SHS;
                ahi[mi][0] = __float_as_uint(sh_hi[r0 + kk]);
                ahi[mi][1] = __float_as_uint(sh_hi[r8 + kk]);
                ahi[mi][2] = __float_as_uint(sh_hi[r0 + kk + 4]);
                ahi[mi][3] = __float_as_uint(sh_hi[r8 + kk + 4]);
                alo[mi][0] = __float_as_uint(sh_lo[r0 + kk]);
                alo[mi][1] = __float_as_uint(sh_lo[r8 + kk]);
                alo[mi][2] = __float_as_uint(sh_lo[r0 + kk + 4]);
                alo[mi][3] = __float_as_uint(sh_lo[r8 + kk + 4]);
            }
#pragma unroll
            for (int mi = 0; mi < 2; mi++)
#pragma unroll
                for (int nj = 0; nj < 2; nj++) {
                    mma_tf32(acc[mi][nj][0], acc[mi][nj][1], acc[mi][nj][2], acc[mi][nj][3],
                             ahi[mi][0], ahi[mi][1], ahi[mi][2], ahi[mi][3],
                             Wh[nj][ks][0], Wh[nj][ks][1]);
                    mma_tf32(acc[mi][nj][0], acc[mi][nj][1], acc[mi][nj][2], acc[mi][nj][3],
                             ahi[mi][0], ahi[mi][1], ahi[mi][2], ahi[mi][3],
                             Wl[nj][ks][0], Wl[nj][ks][1]);
                    mma_tf32(acc[mi][nj][0], acc[mi][nj][1], acc[mi][nj][2], acc[mi][nj][3],
                             alo[mi][0], alo[mi][1], alo[mi][2], alo[mi][3],
                             Wh[nj][ks][0], Wh[nj][ks][1]);
                }
        }

        // --- write partials ---
#pragma unroll
        for (int mi = 0; mi < 2; mi++) {
            const int b0 = mh * 32 + mi * 16 + fr;
#pragma unroll
            for (int nj = 0; nj < 2; nj++) {
                const int n = j0 + nw * 16 + nj * 8 + fc * 2;
                float2 v0, v1;
                v0.x = acc[mi][nj][0]; v0.y = acc[mi][nj][1];
                v1.x = acc[mi][nj][2]; v1.y = acc[mi][nj][3];
                __stcg(reinterpret_cast<float2*>(
                    &g_part[(size_t)(c * BSZ + b0) * HID + n]), v0);
                __stcg(reinterpret_cast<float2*>(
                    &g_part[(size_t)(c * BSZ + b0 + 8) * HID + n]), v1);
            }
        }

        // prefetch U before barrier
        const size_t u0 = ((size_t)t * BSZ + pb_b0) * HID + pb_j0;
        const size_t u1 = ((size_t)t * BSZ + pb_b1) * HID + pb_j1;
        float uv0 = __ldcg(&g_UH[u0]);
        float uv1 = __ldcg(&g_UH[u1]);

        grid_barrier_fast();

        // --- Phase B: reduce + tanh, write h (fp32) and pre-split hi/lo ---
        {
            float v0 = uv0, v1 = uv1;
#pragma unroll
            for (int cc = 0; cc < NC; cc++) {
                v0 += __ldcg(&g_part[(size_t)(cc * BSZ + pb_b0) * HID + pb_j0]);
                v1 += __ldcg(&g_part[(size_t)(cc * BSZ + pb_b1) * HID + pb_j1]);
            }
            v0 = tanhf(v0);
            v1 = tanhf(v1);
            __stcg(&g_UH[u0], v0);
            __stcg(&g_UH[u1], v1);
            uint32_t h0b, l0b, h1b, l1b;
            tf32_split(v0, h0b, l0b);
            tf32_split(v1, h1b, l1b);
            __stcg(&g_Hhi[pb_i0], __uint_as_float(h0b));
            __stcg(&g_Hlo[pb_i0], __uint_as_float(l0b));
            __stcg(&g_Hhi[pb_i1], __uint_as_float(h1b));
            __stcg(&g_Hlo[pb_i1], __uint_as_float(l1b));
        }

        grid_barrier_fast();
    }
}

// ===========================================================================
extern "C" void kernel_launch(void* const* d_in, const int* in_sizes, int n_in,
                              void* d_out, int out_size)
{
    (void)in_sizes; (void)n_in; (void)out_size;
    const float* x     = (const float*)d_in[0];
    const float* h0    = (const float*)d_in[1];
    const float* W_i2h = (const float*)d_in[2];
    const float* b_i2h = (const float*)d_in[3];
    const float* W_h2o = (const float*)d_in[4];
    const float* b_h2o = (const float*)d_in[5];
    float* out = (float*)d_out;

    float* uh = nullptr;
    cudaGetSymbolAddress((void**)&uh, g_UH);

    // 1) U = X @ Wx^T + b_i2h   (bf16x4)
    dim3 g1(HID / BN, (T_STEPS * BSZ) / BM);
    gemm_bf16_k<<<g1, 256>>>(x, NIN, W_i2h, NIN + HID, b_i2h, uh, HID, NIN);

    // 2) sequential recurrence (R7 exact)
    int smem = 2 * 64 * SHS * (int)sizeof(float);
    cudaFuncSetAttribute(rnn_scan_k, cudaFuncAttributeMaxDynamicSharedMemorySize, smem);
    rnn_scan_k<<<RNN_BLOCKS, 256, smem>>>(h0, W_i2h);

    // 3) out = H @ W_h2o^T + b_h2o   (bf16x4)
    dim3 g3(NOUT / BN, (T_STEPS * BSZ) / BM);
    gemm_bf16_k<<<g3, 256>>>(uh, HID, W_h2o, HID, b_h2o, out, NOUT, HID);
}

// round 14
// speedup vs baseline: 1.6432x; 1.0272x over previous
#include <cuda_runtime.h>
#include <cstdint>

#define T_STEPS 512
#define BSZ     64
#define NIN     1024
#define HID     1024
#define NOUT    1024

// recurrence partition
#define NC       8
#define KC       128
#define JT       64
#define RNN_BLOCKS 128
#define SHS      132          // padded smem row stride (floats)

// scratch
__device__ float   g_UH[(size_t)T_STEPS * BSZ * HID];   // U -> h_t (fp32)
__device__ float   g_Hhi[BSZ * HID];                    // tf32-hi of current h
__device__ float   g_Hlo[BSZ * HID];                    // tf32-lo of current h
__device__ float   g_part[NC * BSZ * HID];
__device__ unsigned g_cnt;
__device__ unsigned g_gen;

// ===========================================================================
// common helpers
// ===========================================================================
__device__ __forceinline__ uint32_t smem_u32(const void* p) {
    uint32_t a;
    asm("{ .reg .u64 t; cvta.to.shared.u64 t, %1; cvt.u32.u64 %0, t; }"
        : "=r"(a) : "l"(p));
    return a;
}
__device__ __forceinline__ uint32_t f2tf32(float v) {
    uint32_t r;
    asm("cvt.rna.tf32.f32 %0, %1;" : "=r"(r) : "f"(v));
    return r;
}
__device__ __forceinline__ void tf32_split(float x, uint32_t& hi, uint32_t& lo) {
    hi = f2tf32(x);
    lo = f2tf32(x - __uint_as_float(hi));
}
__device__ __forceinline__ void split4(float4 v, float4& hv, float4& lv) {
    uint32_t h, l;
    tf32_split(v.x, h, l); hv.x = __uint_as_float(h); lv.x = __uint_as_float(l);
    tf32_split(v.y, h, l); hv.y = __uint_as_float(h); lv.y = __uint_as_float(l);
    tf32_split(v.z, h, l); hv.z = __uint_as_float(h); lv.z = __uint_as_float(l);
    tf32_split(v.w, h, l); hv.w = __uint_as_float(h); lv.w = __uint_as_float(l);
}
__device__ __forceinline__ void mma_tf32(
    float& d0, float& d1, float& d2, float& d3,
    uint32_t a0, uint32_t a1, uint32_t a2, uint32_t a3,
    uint32_t b0, uint32_t b1)
{
    asm volatile(
        "mma.sync.aligned.m16n8k8.row.col.f32.tf32.tf32.f32 "
        "{%0,%1,%2,%3}, {%4,%5,%6,%7}, {%8,%9}, {%0,%1,%2,%3};"
        : "+f"(d0), "+f"(d1), "+f"(d2), "+f"(d3)
        : "r"(a0), "r"(a1), "r"(a2), "r"(a3), "r"(b0), "r"(b1));
}
__device__ __forceinline__ void mma_bf16(
    float& d0, float& d1, float& d2, float& d3,
    uint32_t a0, uint32_t a1, uint32_t a2, uint32_t a3,
    uint32_t b0, uint32_t b1)
{
    asm volatile(
        "mma.sync.aligned.m16n8k16.row.col.f32.bf16.bf16.f32 "
        "{%0,%1,%2,%3}, {%4,%5,%6,%7}, {%8,%9}, {%0,%1,%2,%3};"
        : "+f"(d0), "+f"(d1), "+f"(d2), "+f"(d3)
        : "r"(a0), "r"(a1), "r"(a2), "r"(a3), "r"(b0), "r"(b1));
}
__device__ __forceinline__ uint32_t pack_bf16_hi(float f0, float f1) {
    uint32_t r;
    asm("cvt.rn.bf16x2.f32 %0, %1, %2;" : "=r"(r) : "f"(f1), "f"(f0));
    return r;
}
__device__ __forceinline__ uint32_t pack_bf16_lo(uint32_t hi2, float f0, float f1) {
    float h0 = __uint_as_float(hi2 << 16);
    float h1 = __uint_as_float(hi2 & 0xFFFF0000u);
    uint32_t r;
    asm("cvt.rn.bf16x2.f32 %0, %1, %2;" : "=r"(r) : "f"(f1 - h1), "f"(f0 - h0));
    return r;
}
__device__ __forceinline__ void ldsm_x4(
    uint32_t& r0, uint32_t& r1, uint32_t& r2, uint32_t& r3, uint32_t addr)
{
    asm volatile("ldmatrix.sync.aligned.m8n8.x4.shared.b16 {%0,%1,%2,%3}, [%4];"
                 : "=r"(r0), "=r"(r1), "=r"(r2), "=r"(r3) : "r"(addr));
}
__device__ __forceinline__ void ldsm_x2(
    uint32_t& r0, uint32_t& r1, uint32_t addr)
{
    asm volatile("ldmatrix.sync.aligned.m8n8.x2.shared.b16 {%0,%1}, [%2];"
                 : "=r"(r0), "=r"(r1) : "r"(addr));
}

// ===========================================================================
// bf16x3 GEMM with ldmatrix frag loads: C = A@W^T + bias (~fp32 accurate)
// CTA 128x128, BK=16, 8 warps (2x4), warp tile 64x32.
// Loader packs fp32 -> bf16 hi/lo pair-words during STS; mainloop uses
// LDSM x4/x2 (16 LDSM vs 48 LDS.32) + 48 mma (hh, hl, lh; ll dropped).
// ===========================================================================
#define BM 128
#define BN 128
#define SSTB 12                    // bf16-pair words per row (8 + 4 pad)
#define BTILE (BM * SSTB)          // 1536 words = 6KB per tile

__global__ __launch_bounds__(256, 2) void gemm_bf16_k(
    const float* __restrict__ A, int lda,
    const float* __restrict__ Wm, int ldw,
    const float* __restrict__ bias,
    float* __restrict__ C, int ldc, int K)
{
    __shared__ uint32_t Ah[2][BTILE], Al[2][BTILE];
    __shared__ uint32_t Wh[2][BTILE], Wl[2][BTILE];   // 48KB total

    const int tid = threadIdx.x;
    const int wid = tid >> 5;
    const int lane = tid & 31;
    const int m0 = blockIdx.y * BM;
    const int n0 = blockIdx.x * BN;

    const int warp_m = (wid >> 2) * 64;
    const int warp_n = (wid & 3) * 32;

    // loader: row = tid>>1 (0..127), 8 floats at col (tid&1)*8 = 4 k-pairs
    const int lrow = tid >> 1;
    const int lc   = (tid & 1) * 8;
    const int pc0  = (tid & 1) * 4;
    const float* Ag = A  + (size_t)(m0 + lrow) * lda + lc;
    const float* Wg = Wm + (size_t)(n0 + lrow) * ldw + lc;
    const int sbase = lrow * SSTB + pc0;

    // ldmatrix per-lane addressing (byte offsets added to array base)
    const uint32_t uAh = smem_u32(&Ah[0][0]);
    const uint32_t uAl = smem_u32(&Al[0][0]);
    const uint32_t uWh = smem_u32(&Wh[0][0]);
    const uint32_t uWl = smem_u32(&Wl[0][0]);
    const int a_row = warp_m + (lane & 15);       // M0/M1 rows; +16B for M2/M3
    const int a_col = (lane >> 4) << 2;           // words
    const int b_row = warp_n + (lane & 7);
    const int b_col = ((lane >> 3) & 1) << 2;     // words

    const int NK = K / 16;

    float4 pa0 = *reinterpret_cast<const float4*>(Ag);
    float4 pa1 = *reinterpret_cast<const float4*>(Ag + 4);
    float4 pw0 = *reinterpret_cast<const float4*>(Wg);
    float4 pw1 = *reinterpret_cast<const float4*>(Wg + 4);

    // store tile 0
    {
        uint32_t h;
        h = pack_bf16_hi(pa0.x, pa0.y); Ah[0][sbase+0] = h; Al[0][sbase+0] = pack_bf16_lo(h, pa0.x, pa0.y);
        h = pack_bf16_hi(pa0.z, pa0.w); Ah[0][sbase+1] = h; Al[0][sbase+1] = pack_bf16_lo(h, pa0.z, pa0.w);
        h = pack_bf16_hi(pa1.x, pa1.y); Ah[0][sbase+2] = h; Al[0][sbase+2] = pack_bf16_lo(h, pa1.x, pa1.y);
        h = pack_bf16_hi(pa1.z, pa1.w); Ah[0][sbase+3] = h; Al[0][sbase+3] = pack_bf16_lo(h, pa1.z, pa1.w);
        h = pack_bf16_hi(pw0.x, pw0.y); Wh[0][sbase+0] = h; Wl[0][sbase+0] = pack_bf16_lo(h, pw0.x, pw0.y);
        h = pack_bf16_hi(pw0.z, pw0.w); Wh[0][sbase+1] = h; Wl[0][sbase+1] = pack_bf16_lo(h, pw0.z, pw0.w);
        h = pack_bf16_hi(pw1.x, pw1.y); Wh[0][sbase+2] = h; Wl[0][sbase+2] = pack_bf16_lo(h, pw1.x, pw1.y);
        h = pack_bf16_hi(pw1.z, pw1.w); Wh[0][sbase+3] = h; Wl[0][sbase+3] = pack_bf16_lo(h, pw1.z, pw1.w);
    }
    __syncthreads();

    float acc[4][4][4];
#pragma unroll
    for (int i = 0; i < 4; i++)
#pragma unroll
        for (int j = 0; j < 4; j++)
#pragma unroll
            for (int q = 0; q < 4; q++) acc[i][j][q] = 0.0f;

    const int fr = lane >> 2;
    const int fc = lane & 3;

    for (int it = 0; it < NK; it++) {
        const int buf = it & 1;
        const uint32_t bufo = (uint32_t)buf * (BTILE * 4);

        // prefetch next fp32 tile to registers
        if (it + 1 < NK) {
            const float* Ap = Ag + (size_t)(it + 1) * 16;
            const float* Wp = Wg + (size_t)(it + 1) * 16;
            pa0 = *reinterpret_cast<const float4*>(Ap);
            pa1 = *reinterpret_cast<const float4*>(Ap + 4);
            pw0 = *reinterpret_cast<const float4*>(Wp);
            pw1 = *reinterpret_cast<const float4*>(Wp + 4);
        }

        // B fragments via ldmatrix x2 (hi + lo)
        uint32_t bh[4][2], bl[4][2];
#pragma unroll
        for (int j = 0; j < 4; j++) {
            const uint32_t off = (uint32_t)((b_row + j * 8) * SSTB + b_col) * 4u + bufo;
            ldsm_x2(bh[j][0], bh[j][1], uWh + off);
            ldsm_x2(bl[j][0], bl[j][1], uWl + off);
        }

#pragma unroll
        for (int i = 0; i < 4; i++) {
            const uint32_t off = (uint32_t)((a_row + i * 16) * SSTB + a_col) * 4u + bufo;
            uint32_t ah[4], al[4];
            ldsm_x4(ah[0], ah[1], ah[2], ah[3], uAh + off);
            ldsm_x4(al[0], al[1], al[2], al[3], uAl + off);

#pragma unroll
            for (int j = 0; j < 4; j++) {
                mma_bf16(acc[i][j][0], acc[i][j][1], acc[i][j][2], acc[i][j][3],
                         ah[0], ah[1], ah[2], ah[3], bh[j][0], bh[j][1]);
                mma_bf16(acc[i][j][0], acc[i][j][1], acc[i][j][2], acc[i][j][3],
                         ah[0], ah[1], ah[2], ah[3], bl[j][0], bl[j][1]);
                mma_bf16(acc[i][j][0], acc[i][j][1], acc[i][j][2], acc[i][j][3],
                         al[0], al[1], al[2], al[3], bh[j][0], bh[j][1]);
            }
        }

        // store prefetched tile into the OTHER buffer, then publish
        if (it + 1 < NK) {
            const int nb = (it + 1) & 1;
            uint32_t h;
            h = pack_bf16_hi(pa0.x, pa0.y); Ah[nb][sbase+0] = h; Al[nb][sbase+0] = pack_bf16_lo(h, pa0.x, pa0.y);
            h = pack_bf16_hi(pa0.z, pa0.w); Ah[nb][sbase+1] = h; Al[nb][sbase+1] = pack_bf16_lo(h, pa0.z, pa0.w);
            h = pack_bf16_hi(pa1.x, pa1.y); Ah[nb][sbase+2] = h; Al[nb][sbase+2] = pack_bf16_lo(h, pa1.x, pa1.y);
            h = pack_bf16_hi(pa1.z, pa1.w); Ah[nb][sbase+3] = h; Al[nb][sbase+3] = pack_bf16_lo(h, pa1.z, pa1.w);
            h = pack_bf16_hi(pw0.x, pw0.y); Wh[nb][sbase+0] = h; Wl[nb][sbase+0] = pack_bf16_lo(h, pw0.x, pw0.y);
            h = pack_bf16_hi(pw0.z, pw0.w); Wh[nb][sbase+1] = h; Wl[nb][sbase+1] = pack_bf16_lo(h, pw0.z, pw0.w);
            h = pack_bf16_hi(pw1.x, pw1.y); Wh[nb][sbase+2] = h; Wl[nb][sbase+2] = pack_bf16_lo(h, pw1.x, pw1.y);
            h = pack_bf16_hi(pw1.z, pw1.w); Wh[nb][sbase+3] = h; Wl[nb][sbase+3] = pack_bf16_lo(h, pw1.z, pw1.w);
        }
        __syncthreads();
    }

    // epilogue: bias + store
#pragma unroll
    for (int j = 0; j < 4; j++) {
        const int ncol = n0 + warp_n + j * 8 + fc * 2;
        const float2 bv = *reinterpret_cast<const float2*>(&bias[ncol]);
#pragma unroll
        for (int i = 0; i < 4; i++) {
            const int r0 = m0 + warp_m + i * 16 + fr;
            float2 v0, v1;
            v0.x = acc[i][j][0] + bv.x; v0.y = acc[i][j][1] + bv.y;
            v1.x = acc[i][j][2] + bv.x; v1.y = acc[i][j][3] + bv.y;
            *reinterpret_cast<float2*>(&C[(size_t)r0 * ldc + ncol])       = v0;
            *reinterpret_cast<float2*>(&C[(size_t)(r0 + 8) * ldc + ncol]) = v1;
        }
    }
}

// ===========================================================================
// R7 flat atomic grid barrier (measured best of all topologies tried)
// ===========================================================================
__device__ __forceinline__ void grid_barrier_fast()
{
    __syncthreads();
    if (threadIdx.x == 0) {
        unsigned gen;
        asm volatile("ld.acquire.gpu.global.u32 %0, [%1];"
                     : "=r"(gen) : "l"(&g_gen));
        unsigned old;
        asm volatile("atom.acq_rel.gpu.global.add.u32 %0, [%1], 1;"
                     : "=r"(old) : "l"(&g_cnt));
        if (old == gridDim.x - 1) {
            asm volatile("st.relaxed.gpu.global.u32 [%0], 0;"
                         :: "l"(&g_cnt));
            asm volatile("red.release.gpu.global.add.u32 [%0], 1;"
                         :: "l"(&g_gen));
        } else {
            unsigned cur;
            do {
                asm volatile("ld.acquire.gpu.global.u32 %0, [%1];"
                             : "=r"(cur) : "l"(&g_gen));
            } while (cur == gen);
        }
    }
    __syncthreads();
}

// ===========================================================================
// Persistent recurrence (R7 exact — tf32x3 Phase A, flat atomic barriers)
// ===========================================================================
__global__ __launch_bounds__(256) void rnn_scan_k(
    const float* __restrict__ h0, const float* __restrict__ Wi2h)
{
    extern __shared__ float sm[];
    float* sh_hi = sm;                 // [64][SHS]
    float* sh_lo = sm + 64 * SHS;      // [64][SHS]

    const int tid = threadIdx.x;
    const int bid = blockIdx.x;
    const int wid = tid >> 5;
    const int lane = tid & 31;
    const int c   = bid >> 4;
    const int jt  = bid & 15;
    const int j0  = jt * JT;
    const int k0  = c * KC;

    const int mh = wid >> 2;
    const int nw = wid & 3;
    const int fr = lane >> 2;
    const int fc = lane & 3;

    // preload W fragments (loop-invariant)
    uint32_t Wh[2][16][2], Wl[2][16][2];
#pragma unroll
    for (int nj = 0; nj < 2; nj++) {
        const int n = j0 + nw * 16 + nj * 8 + fr;
        const float* wr = &Wi2h[(size_t)n * (NIN + HID) + NIN + k0];
#pragma unroll
        for (int ks = 0; ks < 16; ks++) {
            tf32_split(wr[ks * 8 + fc],     Wh[nj][ks][0], Wl[nj][ks][0]);
            tf32_split(wr[ks * 8 + fc + 4], Wh[nj][ks][1], Wl[nj][ks][1]);
        }
    }

    // Phase B ownership: 512 elements, 2/thread
    const int pb_i0 = bid * 512 + tid;
    const int pb_i1 = bid * 512 + tid + 256;
    const int pb_b0 = pb_i0 >> 10, pb_j0 = pb_i0 & (HID - 1);
    const int pb_b1 = pb_i1 >> 10, pb_j1 = pb_i1 & (HID - 1);

    for (int t = 0; t < T_STEPS; t++) {
        // --- stage h(t-1) chunk into smem (split form) ---
        if (t == 0) {
#pragma unroll
            for (int p = 0; p < 8; p++) {
                const int idx4 = tid + p * 256;
                const int b = idx4 >> 5;
                const int kg = (idx4 & 31) * 4;
                float4 v = *reinterpret_cast<const float4*>(&h0[b * HID + k0 + kg]);
                float4 hv, lv;
                split4(v, hv, lv);
                *reinterpret_cast<float4*>(&sh_hi[b * SHS + kg]) = hv;
                *reinterpret_cast<float4*>(&sh_lo[b * SHS + kg]) = lv;
            }
        } else {
#pragma unroll
            for (int p = 0; p < 8; p++) {
                const int idx4 = tid + p * 256;
                const int b = idx4 >> 5;
                const int kg = (idx4 & 31) * 4;
                const int goff = b * HID + k0 + kg;
                float4 hv = __ldcg(reinterpret_cast<const float4*>(&g_Hhi[goff]));
                float4 lv = __ldcg(reinterpret_cast<const float4*>(&g_Hlo[goff]));
                *reinterpret_cast<float4*>(&sh_hi[b * SHS + kg]) = hv;
                *reinterpret_cast<float4*>(&sh_lo[b * SHS + kg]) = lv;
            }
        }
        __syncthreads();

        // --- Phase A: 3xTF32 mma over 16 k8 steps ---
        float acc[2][2][4];
#pragma unroll
        for (int mi = 0; mi < 2; mi++)
#pragma unroll
            for (int nj = 0; nj < 2; nj++)
#pragma unroll
                for (int q = 0; q < 4; q++) acc[mi][nj][q] = 0.0f;

#pragma unroll
        for (int ks = 0; ks < 16; ks++) {
            const int kk = ks * 8 + fc;
            uint32_t ahi[2][4], alo[2][4];
#pragma unroll
            for (int mi = 0; mi < 2; mi++) {
                const int r0 = (mh * 32 + mi * 16 + fr) * SHS;
                const int r8 = r0 + 8 * SHS;
                ahi[mi][0] = __float_as_uint(sh_hi[r0 + kk]);
                ahi[mi][1] = __float_as_uint(sh_hi[r8 + kk]);
                ahi[mi][2] = __float_as_uint(sh_hi[r0 + kk + 4]);
                ahi[mi][3] = __float_as_uint(sh_hi[r8 + kk + 4]);
                alo[mi][0] = __float_as_uint(sh_lo[r0 + kk]);
                alo[mi][1] = __float_as_uint(sh_lo[r8 + kk]);
                alo[mi][2] = __float_as_uint(sh_lo[r0 + kk + 4]);
                alo[mi][3] = __float_as_uint(sh_lo[r8 + kk + 4]);
            }
#pragma unroll
            for (int mi = 0; mi < 2; mi++)
#pragma unroll
                for (int nj = 0; nj < 2; nj++) {
                    mma_tf32(acc[mi][nj][0], acc[mi][nj][1], acc[mi][nj][2], acc[mi][nj][3],
                             ahi[mi][0], ahi[mi][1], ahi[mi][2], ahi[mi][3],
                             Wh[nj][ks][0], Wh[nj][ks][1]);
                    mma_tf32(acc[mi][nj][0], acc[mi][nj][1], acc[mi][nj][2], acc[mi][nj][3],
                             ahi[mi][0], ahi[mi][1], ahi[mi][2], ahi[mi][3],
                             Wl[nj][ks][0], Wl[nj][ks][1]);
                    mma_tf32(acc[mi][nj][0], acc[mi][nj][1], acc[mi][nj][2], acc[mi][nj][3],
                             alo[mi][0], alo[mi][1], alo[mi][2], alo[mi][3],
                             Wh[nj][ks][0], Wh[nj][ks][1]);
                }
        }

        // --- write partials ---
#pragma unroll
        for (int mi = 0; mi < 2; mi++) {
            const int b0 = mh * 32 + mi * 16 + fr;
#pragma unroll
            for (int nj = 0; nj < 2; nj++) {
                const int n = j0 + nw * 16 + nj * 8 + fc * 2;
                float2 v0, v1;
                v0.x = acc[mi][nj][0]; v0.y = acc[mi][nj][1];
                v1.x = acc[mi][nj][2]; v1.y = acc[mi][nj][3];
                __stcg(reinterpret_cast<float2*>(
                    &g_part[(size_t)(c * BSZ + b0) * HID + n]), v0);
                __stcg(reinterpret_cast<float2*>(
                    &g_part[(size_t)(c * BSZ + b0 + 8) * HID + n]), v1);
            }
        }

        // prefetch U before barrier
        const size_t u0 = ((size_t)t * BSZ + pb_b0) * HID + pb_j0;
        const size_t u1 = ((size_t)t * BSZ + pb_b1) * HID + pb_j1;
        float uv0 = __ldcg(&g_UH[u0]);
        float uv1 = __ldcg(&g_UH[u1]);

        grid_barrier_fast();

        // --- Phase B: reduce + tanh, write h (fp32) and pre-split hi/lo ---
        {
            float v0 = uv0, v1 = uv1;
#pragma unroll
            for (int cc = 0; cc < NC; cc++) {
                v0 += __ldcg(&g_part[(size_t)(cc * BSZ + pb_b0) * HID + pb_j0]);
                v1 += __ldcg(&g_part[(size_t)(cc * BSZ + pb_b1) * HID + pb_j1]);
            }
            v0 = tanhf(v0);
            v1 = tanhf(v1);
            __stcg(&g_UH[u0], v0);
            __stcg(&g_UH[u1], v1);
            uint32_t h0b, l0b, h1b, l1b;
            tf32_split(v0, h0b, l0b);
            tf32_split(v1, h1b, l1b);
            __stcg(&g_Hhi[pb_i0], __uint_as_float(h0b));
            __stcg(&g_Hlo[pb_i0], __uint_as_float(l0b));
            __stcg(&g_Hhi[pb_i1], __uint_as_float(h1b));
            __stcg(&g_Hlo[pb_i1], __uint_as_float(l1b));
        }

        grid_barrier_fast();
    }
}

// ===========================================================================
extern "C" void kernel_launch(void* const* d_in, const int* in_sizes, int n_in,
                              void* d_out, int out_size)
{
    (void)in_sizes; (void)n_in; (void)out_size;
    const float* x     = (const float*)d_in[0];
    const float* h0    = (const float*)d_in[1];
    const float* W_i2h = (const float*)d_in[2];
    const float* b_i2h = (const float*)d_in[3];
    const float* W_h2o = (const float*)d_in[4];
    const float* b_h2o = (const float*)d_in[5];
    float* out = (float*)d_out;

    float* uh = nullptr;
    cudaGetSymbolAddress((void**)&uh, g_UH);

    // 1) U = X @ Wx^T + b_i2h   (bf16x3 + ldmatrix)
    dim3 g1(HID / BN, (T_STEPS * BSZ) / BM);
    gemm_bf16_k<<<g1, 256>>>(x, NIN, W_i2h, NIN + HID, b_i2h, uh, HID, NIN);

    // 2) sequential recurrence (R7 exact)
    int smem = 2 * 64 * SHS * (int)sizeof(float);
    cudaFuncSetAttribute(rnn_scan_k, cudaFuncAttributeMaxDynamicSharedMemorySize, smem);
    rnn_scan_k<<<RNN_BLOCKS, 256, smem>>>(h0, W_i2h);

    // 3) out = H @ W_h2o^T + b_h2o   (bf16x3 + ldmatrix)
    dim3 g3(NOUT / BN, (T_STEPS * BSZ) / BM);
    gemm_bf16_k<<<g3, 256>>>(uh, HID, W_h2o, HID, b_h2o, out, NOUT, HID);
}

// round 15
// speedup vs baseline: 2.0113x; 1.2241x over previous
#include <cuda_runtime.h>
#include <cstdint>

#define T_STEPS 512
#define BSZ     64
#define NIN     1024
#define HID     1024
#define NOUT    1024

// recurrence partition
#define NC       8
#define KC       128
#define JT       64
#define RNN_BLOCKS 128
#define SHS      132          // padded smem row stride (floats)

// scratch (double-buffered by t&1 where cross-step reuse exists)
__device__ float   g_UH[(size_t)T_STEPS * BSZ * HID];      // U -> h_t (fp32)
__device__ float   g_Hhi[2][BSZ * HID];                    // split hi of h
__device__ float   g_Hlo[2][BSZ * HID];                    // split lo of h
__device__ float   g_part[2][NC * BSZ * HID];              // k-split partials
// per-group semaphores (8 groups, one counter per 128B line, monotonic)
__device__ unsigned g_b1[NC * 32];
__device__ unsigned g_b2[NC * 32];
// final global barrier state
__device__ unsigned g_cnt2;
__device__ unsigned g_gen2;

// ===========================================================================
// common helpers
// ===========================================================================
__device__ __forceinline__ uint32_t smem_u32(const void* p) {
    uint32_t a;
    asm("{ .reg .u64 t; cvta.to.shared.u64 t, %1; cvt.u32.u64 %0, t; }"
        : "=r"(a) : "l"(p));
    return a;
}
__device__ __forceinline__ uint32_t f2tf32(float v) {
    uint32_t r;
    asm("cvt.rna.tf32.f32 %0, %1;" : "=r"(r) : "f"(v));
    return r;
}
__device__ __forceinline__ void tf32_split(float x, uint32_t& hi, uint32_t& lo) {
    hi = f2tf32(x);
    lo = f2tf32(x - __uint_as_float(hi));
}
__device__ __forceinline__ void split4(float4 v, float4& hv, float4& lv) {
    uint32_t h, l;
    tf32_split(v.x, h, l); hv.x = __uint_as_float(h); lv.x = __uint_as_float(l);
    tf32_split(v.y, h, l); hv.y = __uint_as_float(h); lv.y = __uint_as_float(l);
    tf32_split(v.z, h, l); hv.z = __uint_as_float(h); lv.z = __uint_as_float(l);
    tf32_split(v.w, h, l); hv.w = __uint_as_float(h); lv.w = __uint_as_float(l);
}
__device__ __forceinline__ void mma_tf32(
    float& d0, float& d1, float& d2, float& d3,
    uint32_t a0, uint32_t a1, uint32_t a2, uint32_t a3,
    uint32_t b0, uint32_t b1)
{
    asm volatile(
        "mma.sync.aligned.m16n8k8.row.col.f32.tf32.tf32.f32 "
        "{%0,%1,%2,%3}, {%4,%5,%6,%7}, {%8,%9}, {%0,%1,%2,%3};"
        : "+f"(d0), "+f"(d1), "+f"(d2), "+f"(d3)
        : "r"(a0), "r"(a1), "r"(a2), "r"(a3), "r"(b0), "r"(b1));
}
__device__ __forceinline__ void mma_bf16(
    float& d0, float& d1, float& d2, float& d3,
    uint32_t a0, uint32_t a1, uint32_t a2, uint32_t a3,
    uint32_t b0, uint32_t b1)
{
    asm volatile(
        "mma.sync.aligned.m16n8k16.row.col.f32.bf16.bf16.f32 "
        "{%0,%1,%2,%3}, {%4,%5,%6,%7}, {%8,%9}, {%0,%1,%2,%3};"
        : "+f"(d0), "+f"(d1), "+f"(d2), "+f"(d3)
        : "r"(a0), "r"(a1), "r"(a2), "r"(a3), "r"(b0), "r"(b1));
}
__device__ __forceinline__ uint32_t pack_bf16_hi(float f0, float f1) {
    uint32_t r;
    asm("cvt.rn.bf16x2.f32 %0, %1, %2;" : "=r"(r) : "f"(f1), "f"(f0));
    return r;
}
__device__ __forceinline__ uint32_t pack_bf16_lo(uint32_t hi2, float f0, float f1) {
    float h0 = __uint_as_float(hi2 << 16);
    float h1 = __uint_as_float(hi2 & 0xFFFF0000u);
    uint32_t r;
    asm("cvt.rn.bf16x2.f32 %0, %1, %2;" : "=r"(r) : "f"(f1 - h1), "f"(f0 - h0));
    return r;
}
__device__ __forceinline__ void ldsm_x4(
    uint32_t& r0, uint32_t& r1, uint32_t& r2, uint32_t& r3, uint32_t addr)
{
    asm volatile("ldmatrix.sync.aligned.m8n8.x4.shared.b16 {%0,%1,%2,%3}, [%4];"
                 : "=r"(r0), "=r"(r1), "=r"(r2), "=r"(r3) : "r"(addr));
}
__device__ __forceinline__ void ldsm_x2(
    uint32_t& r0, uint32_t& r1, uint32_t addr)
{
    asm volatile("ldmatrix.sync.aligned.m8n8.x2.shared.b16 {%0,%1}, [%2];"
                 : "=r"(r0), "=r"(r1) : "r"(addr));
}

// ===========================================================================
// bf16x3 GEMM with ldmatrix frag loads (R14 exact — known good, ~716us)
// ===========================================================================
#define BM 128
#define BN 128
#define SSTB 12
#define BTILE (BM * SSTB)

__global__ __launch_bounds__(256, 2) void gemm_bf16_k(
    const float* __restrict__ A, int lda,
    const float* __restrict__ Wm, int ldw,
    const float* __restrict__ bias,
    float* __restrict__ C, int ldc, int K)
{
    __shared__ uint32_t Ah[2][BTILE], Al[2][BTILE];
    __shared__ uint32_t Wh[2][BTILE], Wl[2][BTILE];

    const int tid = threadIdx.x;
    const int wid = tid >> 5;
    const int lane = tid & 31;
    const int m0 = blockIdx.y * BM;
    const int n0 = blockIdx.x * BN;

    const int warp_m = (wid >> 2) * 64;
    const int warp_n = (wid & 3) * 32;

    const int lrow = tid >> 1;
    const int lc   = (tid & 1) * 8;
    const int pc0  = (tid & 1) * 4;
    const float* Ag = A  + (size_t)(m0 + lrow) * lda + lc;
    const float* Wg = Wm + (size_t)(n0 + lrow) * ldw + lc;
    const int sbase = lrow * SSTB + pc0;

    const uint32_t uAh = smem_u32(&Ah[0][0]);
    const uint32_t uAl = smem_u32(&Al[0][0]);
    const uint32_t uWh = smem_u32(&Wh[0][0]);
    const uint32_t uWl = smem_u32(&Wl[0][0]);
    const int a_row = warp_m + (lane & 15);
    const int a_col = (lane >> 4) << 2;
    const int b_row = warp_n + (lane & 7);
    const int b_col = ((lane >> 3) & 1) << 2;

    const int NK = K / 16;

    float4 pa0 = *reinterpret_cast<const float4*>(Ag);
    float4 pa1 = *reinterpret_cast<const float4*>(Ag + 4);
    float4 pw0 = *reinterpret_cast<const float4*>(Wg);
    float4 pw1 = *reinterpret_cast<const float4*>(Wg + 4);

    {
        uint32_t h;
        h = pack_bf16_hi(pa0.x, pa0.y); Ah[0][sbase+0] = h; Al[0][sbase+0] = pack_bf16_lo(h, pa0.x, pa0.y);
        h = pack_bf16_hi(pa0.z, pa0.w); Ah[0][sbase+1] = h; Al[0][sbase+1] = pack_bf16_lo(h, pa0.z, pa0.w);
        h = pack_bf16_hi(pa1.x, pa1.y); Ah[0][sbase+2] = h; Al[0][sbase+2] = pack_bf16_lo(h, pa1.x, pa1.y);
        h = pack_bf16_hi(pa1.z, pa1.w); Ah[0][sbase+3] = h; Al[0][sbase+3] = pack_bf16_lo(h, pa1.z, pa1.w);
        h = pack_bf16_hi(pw0.x, pw0.y); Wh[0][sbase+0] = h; Wl[0][sbase+0] = pack_bf16_lo(h, pw0.x, pw0.y);
        h = pack_bf16_hi(pw0.z, pw0.w); Wh[0][sbase+1] = h; Wl[0][sbase+1] = pack_bf16_lo(h, pw0.z, pw0.w);
        h = pack_bf16_hi(pw1.x, pw1.y); Wh[0][sbase+2] = h; Wl[0][sbase+2] = pack_bf16_lo(h, pw1.x, pw1.y);
        h = pack_bf16_hi(pw1.z, pw1.w); Wh[0][sbase+3] = h; Wl[0][sbase+3] = pack_bf16_lo(h, pw1.z, pw1.w);
    }
    __syncthreads();

    float acc[4][4][4];
#pragma unroll
    for (int i = 0; i < 4; i++)
#pragma unroll
        for (int j = 0; j < 4; j++)
#pragma unroll
            for (int q = 0; q < 4; q++) acc[i][j][q] = 0.0f;

    const int fr = lane >> 2;
    const int fc = lane & 3;

    for (int it = 0; it < NK; it++) {
        const int buf = it & 1;
        const uint32_t bufo = (uint32_t)buf * (BTILE * 4);

        if (it + 1 < NK) {
            const float* Ap = Ag + (size_t)(it + 1) * 16;
            const float* Wp = Wg + (size_t)(it + 1) * 16;
            pa0 = *reinterpret_cast<const float4*>(Ap);
            pa1 = *reinterpret_cast<const float4*>(Ap + 4);
            pw0 = *reinterpret_cast<const float4*>(Wp);
            pw1 = *reinterpret_cast<const float4*>(Wp + 4);
        }

        uint32_t bh[4][2], bl[4][2];
#pragma unroll
        for (int j = 0; j < 4; j++) {
            const uint32_t off = (uint32_t)((b_row + j * 8) * SSTB + b_col) * 4u + bufo;
            ldsm_x2(bh[j][0], bh[j][1], uWh + off);
            ldsm_x2(bl[j][0], bl[j][1], uWl + off);
        }

#pragma unroll
        for (int i = 0; i < 4; i++) {
            const uint32_t off = (uint32_t)((a_row + i * 16) * SSTB + a_col) * 4u + bufo;
            uint32_t ah[4], al[4];
            ldsm_x4(ah[0], ah[1], ah[2], ah[3], uAh + off);
            ldsm_x4(al[0], al[1], al[2], al[3], uAl + off);

#pragma unroll
            for (int j = 0; j < 4; j++) {
                mma_bf16(acc[i][j][0], acc[i][j][1], acc[i][j][2], acc[i][j][3],
                         ah[0], ah[1], ah[2], ah[3], bh[j][0], bh[j][1]);
                mma_bf16(acc[i][j][0], acc[i][j][1], acc[i][j][2], acc[i][j][3],
                         ah[0], ah[1], ah[2], ah[3], bl[j][0], bl[j][1]);
                mma_bf16(acc[i][j][0], acc[i][j][1], acc[i][j][2], acc[i][j][3],
                         al[0], al[1], al[2], al[3], bh[j][0], bh[j][1]);
            }
        }

        if (it + 1 < NK) {
            const int nb = (it + 1) & 1;
            uint32_t h;
            h = pack_bf16_hi(pa0.x, pa0.y); Ah[nb][sbase+0] = h; Al[nb][sbase+0] = pack_bf16_lo(h, pa0.x, pa0.y);
            h = pack_bf16_hi(pa0.z, pa0.w); Ah[nb][sbase+1] = h; Al[nb][sbase+1] = pack_bf16_lo(h, pa0.z, pa0.w);
            h = pack_bf16_hi(pa1.x, pa1.y); Ah[nb][sbase+2] = h; Al[nb][sbase+2] = pack_bf16_lo(h, pa1.x, pa1.y);
            h = pack_bf16_hi(pa1.z, pa1.w); Ah[nb][sbase+3] = h; Al[nb][sbase+3] = pack_bf16_lo(h, pa1.z, pa1.w);
            h = pack_bf16_hi(pw0.x, pw0.y); Wh[nb][sbase+0] = h; Wl[nb][sbase+0] = pack_bf16_lo(h, pw0.x, pw0.y);
            h = pack_bf16_hi(pw0.z, pw0.w); Wh[nb][sbase+1] = h; Wl[nb][sbase+1] = pack_bf16_lo(h, pw0.z, pw0.w);
            h = pack_bf16_hi(pw1.x, pw1.y); Wh[nb][sbase+2] = h; Wl[nb][sbase+2] = pack_bf16_lo(h, pw1.x, pw1.y);
            h = pack_bf16_hi(pw1.z, pw1.w); Wh[nb][sbase+3] = h; Wl[nb][sbase+3] = pack_bf16_lo(h, pw1.z, pw1.w);
        }
        __syncthreads();
    }

#pragma unroll
    for (int j = 0; j < 4; j++) {
        const int ncol = n0 + warp_n + j * 8 + fc * 2;
        const float2 bv = *reinterpret_cast<const float2*>(&bias[ncol]);
#pragma unroll
        for (int i = 0; i < 4; i++) {
            const int r0 = m0 + warp_m + i * 16 + fr;
            float2 v0, v1;
            v0.x = acc[i][j][0] + bv.x; v0.y = acc[i][j][1] + bv.y;
            v1.x = acc[i][j][2] + bv.x; v1.y = acc[i][j][3] + bv.y;
            *reinterpret_cast<float2*>(&C[(size_t)r0 * ldc + ncol])       = v0;
            *reinterpret_cast<float2*>(&C[(size_t)(r0 + 8) * ldc + ncol]) = v1;
        }
    }
}

// ===========================================================================
// global atomic barrier (only used once at scan end for counter reset)
// ===========================================================================
__device__ __forceinline__ void grid_barrier_atomic()
{
    __syncthreads();
    if (threadIdx.x == 0) {
        unsigned gen;
        asm volatile("ld.acquire.gpu.global.u32 %0, [%1];"
                     : "=r"(gen) : "l"(&g_gen2));
        unsigned old;
        asm volatile("atom.acq_rel.gpu.global.add.u32 %0, [%1], 1;"
                     : "=r"(old) : "l"(&g_cnt2));
        if (old == gridDim.x - 1) {
            asm volatile("st.relaxed.gpu.global.u32 [%0], 0;"
                         :: "l"(&g_cnt2));
            asm volatile("red.release.gpu.global.add.u32 [%0], 1;"
                         :: "l"(&g_gen2));
        } else {
            unsigned cur;
            do {
                asm volatile("ld.acquire.gpu.global.u32 %0, [%1];"
                             : "=r"(cur) : "l"(&g_gen2));
            } while (cur == gen);
        }
    }
    __syncthreads();
}

// ===========================================================================
// Persistent recurrence with per-group (16-block) semaphores.
// Group c = blocks (c, jt=0..15). Phase B: block (c,jt) reduces
// h[4jt..4jt+3][k0..k0+127] so group c produces exactly the columns it
// stages next step. B1[c]: 16 producers (cc, 2c|2c+1) arrive post-partials;
// group c waits. B2[c]: group-internal barrier after h writes. g_part and
// g_Hhi/g_Hlo double-buffered by t&1 (2-step reuse distance is covered by
// B1's all-group producer fan-in, transitively).
// ===========================================================================
__global__ __launch_bounds__(256) void rnn_scan_k(
    const float* __restrict__ h0, const float* __restrict__ Wi2h)
{
    extern __shared__ float sm[];
    float* sh_hi = sm;                 // [64][SHS]
    float* sh_lo = sm + 64 * SHS;      // [64][SHS]

    const int tid = threadIdx.x;
    const int bid = blockIdx.x;
    const int wid = tid >> 5;
    const int lane = tid & 31;
    const int c   = bid >> 4;
    const int jt  = bid & 15;
    const int j0  = jt * JT;
    const int k0  = c * KC;

    const int mh = wid >> 2;
    const int nw = wid & 3;
    const int fr = lane >> 2;
    const int fc = lane & 3;

    // preload W fragments (loop-invariant)
    uint32_t Wh[2][16][2], Wl[2][16][2];
#pragma unroll
    for (int nj = 0; nj < 2; nj++) {
        const int n = j0 + nw * 16 + nj * 8 + fr;
        const float* wr = &Wi2h[(size_t)n * (NIN + HID) + NIN + k0];
#pragma unroll
        for (int ks = 0; ks < 16; ks++) {
            tf32_split(wr[ks * 8 + fc],     Wh[nj][ks][0], Wl[nj][ks][0]);
            tf32_split(wr[ks * 8 + fc + 4], Wh[nj][ks][1], Wl[nj][ks][1]);
        }
    }

    // Phase B ownership: rows 4jt..4jt+3, cols k0..k0+127; 2 cols/thread
    const int pb_e   = 2 * tid;
    const int pb_b   = 4 * jt + (pb_e >> 7);
    const int pb_col = k0 + (pb_e & 127);
    unsigned* const b1_arr  = &g_b1[(jt >> 1) * 32];
    unsigned* const b1_wait = &g_b1[c * 32];
    unsigned* const b2_sem  = &g_b2[c * 32];

    for (int t = 0; t < T_STEPS; t++) {
        const int par = t & 1;

        // --- stage h(t-1) chunk (cols k0..k0+127, all 64 b) ---
        if (t == 0) {
#pragma unroll
            for (int p = 0; p < 8; p++) {
                const int idx4 = tid + p * 256;
                const int b = idx4 >> 5;
                const int kg = (idx4 & 31) * 4;
                float4 v = *reinterpret_cast<const float4*>(&h0[b * HID + k0 + kg]);
                float4 hv, lv;
                split4(v, hv, lv);
                *reinterpret_cast<float4*>(&sh_hi[b * SHS + kg]) = hv;
                *reinterpret_cast<float4*>(&sh_lo[b * SHS + kg]) = lv;
            }
        } else {
            const float* srchi = g_Hhi[(t - 1) & 1];
            const float* srclo = g_Hlo[(t - 1) & 1];
#pragma unroll
            for (int p = 0; p < 8; p++) {
                const int idx4 = tid + p * 256;
                const int b = idx4 >> 5;
                const int kg = (idx4 & 31) * 4;
                const int goff = b * HID + k0 + kg;
                float4 hv = __ldcg(reinterpret_cast<const float4*>(&srchi[goff]));
                float4 lv = __ldcg(reinterpret_cast<const float4*>(&srclo[goff]));
                *reinterpret_cast<float4*>(&sh_hi[b * SHS + kg]) = hv;
                *reinterpret_cast<float4*>(&sh_lo[b * SHS + kg]) = lv;
            }
        }
        __syncthreads();

        // --- Phase A: 3xTF32 mma over 16 k8 steps ---
        float acc[2][2][4];
#pragma unroll
        for (int mi = 0; mi < 2; mi++)
#pragma unroll
            for (int nj = 0; nj < 2; nj++)
#pragma unroll
                for (int q = 0; q < 4; q++) acc[mi][nj][q] = 0.0f;

#pragma unroll
        for (int ks = 0; ks < 16; ks++) {
            const int kk = ks * 8 + fc;
            uint32_t ahi[2][4], alo[2][4];
#pragma unroll
            for (int mi = 0; mi < 2; mi++) {
                const int r0 = (mh * 32 + mi * 16 + fr) * SHS;
                const int r8 = r0 + 8 * SHS;
                ahi[mi][0] = __float_as_uint(sh_hi[r0 + kk]);
                ahi[mi][1] = __float_as_uint(sh_hi[r8 + kk]);
                ahi[mi][2] = __float_as_uint(sh_hi[r0 + kk + 4]);
                ahi[mi][3] = __float_as_uint(sh_hi[r8 + kk + 4]);
                alo[mi][0] = __float_as_uint(sh_lo[r0 + kk]);
                alo[mi][1] = __float_as_uint(sh_lo[r8 + kk]);
                alo[mi][2] = __float_as_uint(sh_lo[r0 + kk + 4]);
                alo[mi][3] = __float_as_uint(sh_lo[r8 + kk + 4]);
            }
#pragma unroll
            for (int mi = 0; mi < 2; mi++)
#pragma unroll
                for (int nj = 0; nj < 2; nj++) {
                    mma_tf32(acc[mi][nj][0], acc[mi][nj][1], acc[mi][nj][2], acc[mi][nj][3],
                             ahi[mi][0], ahi[mi][1], ahi[mi][2], ahi[mi][3],
                             Wh[nj][ks][0], Wh[nj][ks][1]);
                    mma_tf32(acc[mi][nj][0], acc[mi][nj][1], acc[mi][nj][2], acc[mi][nj][3],
                             ahi[mi][0], ahi[mi][1], ahi[mi][2], ahi[mi][3],
                             Wl[nj][ks][0], Wl[nj][ks][1]);
                    mma_tf32(acc[mi][nj][0], acc[mi][nj][1], acc[mi][nj][2], acc[mi][nj][3],
                             alo[mi][0], alo[mi][1], alo[mi][2], alo[mi][3],
                             Wh[nj][ks][0], Wh[nj][ks][1]);
                }
        }

        // --- write partials into buffer par ---
        float* partbuf = g_part[par];
#pragma unroll
        for (int mi = 0; mi < 2; mi++) {
            const int b0 = mh * 32 + mi * 16 + fr;
#pragma unroll
            for (int nj = 0; nj < 2; nj++) {
                const int n = j0 + nw * 16 + nj * 8 + fc * 2;
                float2 v0, v1;
                v0.x = acc[mi][nj][0]; v0.y = acc[mi][nj][1];
                v1.x = acc[mi][nj][2]; v1.y = acc[mi][nj][3];
                __stcg(reinterpret_cast<float2*>(
                    &partbuf[(size_t)(c * BSZ + b0) * HID + n]), v0);
                __stcg(reinterpret_cast<float2*>(
                    &partbuf[(size_t)(c * BSZ + b0 + 8) * HID + n]), v1);
            }
        }

        // prefetch U before the wait
        const size_t u0 = ((size_t)t * BSZ + pb_b) * HID + pb_col;
        float2 uv = __ldcg(reinterpret_cast<const float2*>(&g_UH[u0]));

        // --- B1: arrive for consumer group (jt>>1); wait own 16 producers ---
        __syncthreads();
        if (tid == 0) {
            asm volatile("red.release.gpu.global.add.u32 [%0], 1;" :: "l"(b1_arr));
            const unsigned want = 16u * (unsigned)(t + 1);
            unsigned v;
            do {
                asm volatile("ld.acquire.gpu.global.u32 %0, [%1];"
                             : "=r"(v) : "l"(b1_wait));
            } while (v < want);
        }
        __syncthreads();

        // --- Phase B: reduce own 512 elems, tanh, write fp32 h + splits ---
        {
            float v0 = uv.x, v1 = uv.y;
#pragma unroll
            for (int cc = 0; cc < NC; cc++) {
                float2 p = __ldcg(reinterpret_cast<const float2*>(
                    &partbuf[(size_t)(cc * BSZ + pb_b) * HID + pb_col]));
                v0 += p.x;
                v1 += p.y;
            }
            v0 = tanhf(v0);
            v1 = tanhf(v1);
            float2 hw; hw.x = v0; hw.y = v1;
            __stcg(reinterpret_cast<float2*>(&g_UH[u0]), hw);   // h for GEMM3
            uint32_t h0b, l0b, h1b, l1b;
            tf32_split(v0, h0b, l0b);
            tf32_split(v1, h1b, l1b);
            float2 hv, lv;
            hv.x = __uint_as_float(h0b); hv.y = __uint_as_float(h1b);
            lv.x = __uint_as_float(l0b); lv.y = __uint_as_float(l1b);
            const int ho = pb_b * HID + pb_col;
            __stcg(reinterpret_cast<float2*>(&g_Hhi[par][ho]), hv);
            __stcg(reinterpret_cast<float2*>(&g_Hlo[par][ho]), lv);
        }

        // --- B2: group-c internal barrier (h columns of group c ready) ---
        __syncthreads();
        if (tid == 0) {
            asm volatile("red.release.gpu.global.add.u32 [%0], 1;" :: "l"(b2_sem));
            const unsigned want = 16u * (unsigned)(t + 1);
            unsigned v;
            do {
                asm volatile("ld.acquire.gpu.global.u32 %0, [%1];"
                             : "=r"(v) : "l"(b2_sem));
            } while (v < want);
        }
        __syncthreads();
    }

    // reset semaphores for the next graph replay, behind a global barrier
    grid_barrier_atomic();
    if (jt == 0 && tid == 0) {
        asm volatile("st.relaxed.gpu.global.u32 [%0], 0;" :: "l"(&g_b1[c * 32]));
        asm volatile("st.relaxed.gpu.global.u32 [%0], 0;" :: "l"(&g_b2[c * 32]));
    }
}

// ===========================================================================
extern "C" void kernel_launch(void* const* d_in, const int* in_sizes, int n_in,
                              void* d_out, int out_size)
{
    (void)in_sizes; (void)n_in; (void)out_size;
    const float* x     = (const float*)d_in[0];
    const float* h0    = (const float*)d_in[1];
    const float* W_i2h = (const float*)d_in[2];
    const float* b_i2h = (const float*)d_in[3];
    const float* W_h2o = (const float*)d_in[4];
    const float* b_h2o = (const float*)d_in[5];
    float* out = (float*)d_out;

    float* uh = nullptr;
    cudaGetSymbolAddress((void**)&uh, g_UH);

    // 1) U = X @ Wx^T + b_i2h   (bf16x3 + ldmatrix)
    dim3 g1(HID / BN, (T_STEPS * BSZ) / BM);
    gemm_bf16_k<<<g1, 256>>>(x, NIN, W_i2h, NIN + HID, b_i2h, uh, HID, NIN);

    // 2) sequential recurrence (group-semaphore sync)
    int smem = 2 * 64 * SHS * (int)sizeof(float);
    cudaFuncSetAttribute(rnn_scan_k, cudaFuncAttributeMaxDynamicSharedMemorySize, smem);
    rnn_scan_k<<<RNN_BLOCKS, 256, smem>>>(h0, W_i2h);

    // 3) out = H @ W_h2o^T + b_h2o   (bf16x3 + ldmatrix)
    gemm_bf16_k<<<g1, 256>>>(uh, HID, W_h2o, HID, b_h2o, out, NOUT, HID);
}

// round 16
// speedup vs baseline: 2.3401x; 1.1635x over previous
#include <cuda_runtime.h>
#include <cstdint>

#define T_STEPS 512
#define BSZ     64
#define NIN     1024
#define HID     1024
#define NOUT    1024

// recurrence partition
#define NC       8
#define KC       128
#define JT       64
#define RNN_BLOCKS 128
#define SSB      68           // scan smem pair-word row stride (64 + 4 pad)

// scratch (double-buffered by t&1 where cross-step reuse exists)
__device__ float    g_UH[(size_t)T_STEPS * BSZ * HID];     // U -> h_t (fp32)
__device__ uint32_t g_Hbfhi[2][BSZ * HID / 2];             // bf16x2 hi of h
__device__ uint32_t g_Hbflo[2][BSZ * HID / 2];             // bf16x2 lo of h
__device__ float    g_part[2][NC * BSZ * HID];             // k-split partials
// per-group semaphores (8 groups, one counter per 128B line, monotonic)
__device__ unsigned g_b1[NC * 32];
__device__ unsigned g_b2[NC * 32];
// final global barrier state
__device__ unsigned g_cnt2;
__device__ unsigned g_gen2;

// ===========================================================================
// common helpers
// ===========================================================================
__device__ __forceinline__ uint32_t smem_u32(const void* p) {
    uint32_t a;
    asm("{ .reg .u64 t; cvta.to.shared.u64 t, %1; cvt.u32.u64 %0, t; }"
        : "=r"(a) : "l"(p));
    return a;
}
__device__ __forceinline__ void mma_bf16(
    float& d0, float& d1, float& d2, float& d3,
    uint32_t a0, uint32_t a1, uint32_t a2, uint32_t a3,
    uint32_t b0, uint32_t b1)
{
    asm volatile(
        "mma.sync.aligned.m16n8k16.row.col.f32.bf16.bf16.f32 "
        "{%0,%1,%2,%3}, {%4,%5,%6,%7}, {%8,%9}, {%0,%1,%2,%3};"
        : "+f"(d0), "+f"(d1), "+f"(d2), "+f"(d3)
        : "r"(a0), "r"(a1), "r"(a2), "r"(a3), "r"(b0), "r"(b1));
}
__device__ __forceinline__ uint32_t pack_bf16_hi(float f0, float f1) {
    uint32_t r;
    asm("cvt.rn.bf16x2.f32 %0, %1, %2;" : "=r"(r) : "f"(f1), "f"(f0));
    return r;
}
__device__ __forceinline__ uint32_t pack_bf16_lo(uint32_t hi2, float f0, float f1) {
    float h0 = __uint_as_float(hi2 << 16);
    float h1 = __uint_as_float(hi2 & 0xFFFF0000u);
    uint32_t r;
    asm("cvt.rn.bf16x2.f32 %0, %1, %2;" : "=r"(r) : "f"(f1 - h1), "f"(f0 - h0));
    return r;
}
__device__ __forceinline__ void ldsm_x4(
    uint32_t& r0, uint32_t& r1, uint32_t& r2, uint32_t& r3, uint32_t addr)
{
    asm volatile("ldmatrix.sync.aligned.m8n8.x4.shared.b16 {%0,%1,%2,%3}, [%4];"
                 : "=r"(r0), "=r"(r1), "=r"(r2), "=r"(r3) : "r"(addr));
}
__device__ __forceinline__ void ldsm_x2(
    uint32_t& r0, uint32_t& r1, uint32_t addr)
{
    asm volatile("ldmatrix.sync.aligned.m8n8.x2.shared.b16 {%0,%1}, [%2];"
                 : "=r"(r0), "=r"(r1) : "r"(addr));
}

// ===========================================================================
// bf16x3 GEMM with ldmatrix frag loads (R14 exact — known good, ~716us)
// ===========================================================================
#define BM 128
#define BN 128
#define SSTB 12
#define BTILE (BM * SSTB)

__global__ __launch_bounds__(256, 2) void gemm_bf16_k(
    const float* __restrict__ A, int lda,
    const float* __restrict__ Wm, int ldw,
    const float* __restrict__ bias,
    float* __restrict__ C, int ldc, int K)
{
    __shared__ uint32_t Ah[2][BTILE], Al[2][BTILE];
    __shared__ uint32_t Wh[2][BTILE], Wl[2][BTILE];

    const int tid = threadIdx.x;
    const int wid = tid >> 5;
    const int lane = tid & 31;
    const int m0 = blockIdx.y * BM;
    const int n0 = blockIdx.x * BN;

    const int warp_m = (wid >> 2) * 64;
    const int warp_n = (wid & 3) * 32;

    const int lrow = tid >> 1;
    const int lc   = (tid & 1) * 8;
    const int pc0  = (tid & 1) * 4;
    const float* Ag = A  + (size_t)(m0 + lrow) * lda + lc;
    const float* Wg = Wm + (size_t)(n0 + lrow) * ldw + lc;
    const int sbase = lrow * SSTB + pc0;

    const uint32_t uAh = smem_u32(&Ah[0][0]);
    const uint32_t uAl = smem_u32(&Al[0][0]);
    const uint32_t uWh = smem_u32(&Wh[0][0]);
    const uint32_t uWl = smem_u32(&Wl[0][0]);
    const int a_row = warp_m + (lane & 15);
    const int a_col = (lane >> 4) << 2;
    const int b_row = warp_n + (lane & 7);
    const int b_col = ((lane >> 3) & 1) << 2;

    const int NK = K / 16;

    float4 pa0 = *reinterpret_cast<const float4*>(Ag);
    float4 pa1 = *reinterpret_cast<const float4*>(Ag + 4);
    float4 pw0 = *reinterpret_cast<const float4*>(Wg);
    float4 pw1 = *reinterpret_cast<const float4*>(Wg + 4);

    {
        uint32_t h;
        h = pack_bf16_hi(pa0.x, pa0.y); Ah[0][sbase+0] = h; Al[0][sbase+0] = pack_bf16_lo(h, pa0.x, pa0.y);
        h = pack_bf16_hi(pa0.z, pa0.w); Ah[0][sbase+1] = h; Al[0][sbase+1] = pack_bf16_lo(h, pa0.z, pa0.w);
        h = pack_bf16_hi(pa1.x, pa1.y); Ah[0][sbase+2] = h; Al[0][sbase+2] = pack_bf16_lo(h, pa1.x, pa1.y);
        h = pack_bf16_hi(pa1.z, pa1.w); Ah[0][sbase+3] = h; Al[0][sbase+3] = pack_bf16_lo(h, pa1.z, pa1.w);
        h = pack_bf16_hi(pw0.x, pw0.y); Wh[0][sbase+0] = h; Wl[0][sbase+0] = pack_bf16_lo(h, pw0.x, pw0.y);
        h = pack_bf16_hi(pw0.z, pw0.w); Wh[0][sbase+1] = h; Wl[0][sbase+1] = pack_bf16_lo(h, pw0.z, pw0.w);
        h = pack_bf16_hi(pw1.x, pw1.y); Wh[0][sbase+2] = h; Wl[0][sbase+2] = pack_bf16_lo(h, pw1.x, pw1.y);
        h = pack_bf16_hi(pw1.z, pw1.w); Wh[0][sbase+3] = h; Wl[0][sbase+3] = pack_bf16_lo(h, pw1.z, pw1.w);
    }
    __syncthreads();

    float acc[4][4][4];
#pragma unroll
    for (int i = 0; i < 4; i++)
#pragma unroll
        for (int j = 0; j < 4; j++)
#pragma unroll
            for (int q = 0; q < 4; q++) acc[i][j][q] = 0.0f;

    const int fr = lane >> 2;
    const int fc = lane & 3;

    for (int it = 0; it < NK; it++) {
        const int buf = it & 1;
        const uint32_t bufo = (uint32_t)buf * (BTILE * 4);

        if (it + 1 < NK) {
            const float* Ap = Ag + (size_t)(it + 1) * 16;
            const float* Wp = Wg + (size_t)(it + 1) * 16;
            pa0 = *reinterpret_cast<const float4*>(Ap);
            pa1 = *reinterpret_cast<const float4*>(Ap + 4);
            pw0 = *reinterpret_cast<const float4*>(Wp);
            pw1 = *reinterpret_cast<const float4*>(Wp + 4);
        }

        uint32_t bh[4][2], bl[4][2];
#pragma unroll
        for (int j = 0; j < 4; j++) {
            const uint32_t off = (uint32_t)((b_row + j * 8) * SSTB + b_col) * 4u + bufo;
            ldsm_x2(bh[j][0], bh[j][1], uWh + off);
            ldsm_x2(bl[j][0], bl[j][1], uWl + off);
        }

#pragma unroll
        for (int i = 0; i < 4; i++) {
            const uint32_t off = (uint32_t)((a_row + i * 16) * SSTB + a_col) * 4u + bufo;
            uint32_t ah[4], al[4];
            ldsm_x4(ah[0], ah[1], ah[2], ah[3], uAh + off);
            ldsm_x4(al[0], al[1], al[2], al[3], uAl + off);

#pragma unroll
            for (int j = 0; j < 4; j++) {
                mma_bf16(acc[i][j][0], acc[i][j][1], acc[i][j][2], acc[i][j][3],
                         ah[0], ah[1], ah[2], ah[3], bh[j][0], bh[j][1]);
                mma_bf16(acc[i][j][0], acc[i][j][1], acc[i][j][2], acc[i][j][3],
                         ah[0], ah[1], ah[2], ah[3], bl[j][0], bl[j][1]);
                mma_bf16(acc[i][j][0], acc[i][j][1], acc[i][j][2], acc[i][j][3],
                         al[0], al[1], al[2], al[3], bh[j][0], bh[j][1]);
            }
        }

        if (it + 1 < NK) {
            const int nb = (it + 1) & 1;
            uint32_t h;
            h = pack_bf16_hi(pa0.x, pa0.y); Ah[nb][sbase+0] = h; Al[nb][sbase+0] = pack_bf16_lo(h, pa0.x, pa0.y);
            h = pack_bf16_hi(pa0.z, pa0.w); Ah[nb][sbase+1] = h; Al[nb][sbase+1] = pack_bf16_lo(h, pa0.z, pa0.w);
            h = pack_bf16_hi(pa1.x, pa1.y); Ah[nb][sbase+2] = h; Al[nb][sbase+2] = pack_bf16_lo(h, pa1.x, pa1.y);
            h = pack_bf16_hi(pa1.z, pa1.w); Ah[nb][sbase+3] = h; Al[nb][sbase+3] = pack_bf16_lo(h, pa1.z, pa1.w);
            h = pack_bf16_hi(pw0.x, pw0.y); Wh[nb][sbase+0] = h; Wl[nb][sbase+0] = pack_bf16_lo(h, pw0.x, pw0.y);
            h = pack_bf16_hi(pw0.z, pw0.w); Wh[nb][sbase+1] = h; Wl[nb][sbase+1] = pack_bf16_lo(h, pw0.z, pw0.w);
            h = pack_bf16_hi(pw1.x, pw1.y); Wh[nb][sbase+2] = h; Wl[nb][sbase+2] = pack_bf16_lo(h, pw1.x, pw1.y);
            h = pack_bf16_hi(pw1.z, pw1.w); Wh[nb][sbase+3] = h; Wl[nb][sbase+3] = pack_bf16_lo(h, pw1.z, pw1.w);
        }
        __syncthreads();
    }

#pragma unroll
    for (int j = 0; j < 4; j++) {
        const int ncol = n0 + warp_n + j * 8 + fc * 2;
        const float2 bv = *reinterpret_cast<const float2*>(&bias[ncol]);
#pragma unroll
        for (int i = 0; i < 4; i++) {
            const int r0 = m0 + warp_m + i * 16 + fr;
            float2 v0, v1;
            v0.x = acc[i][j][0] + bv.x; v0.y = acc[i][j][1] + bv.y;
            v1.x = acc[i][j][2] + bv.x; v1.y = acc[i][j][3] + bv.y;
            *reinterpret_cast<float2*>(&C[(size_t)r0 * ldc + ncol])       = v0;
            *reinterpret_cast<float2*>(&C[(size_t)(r0 + 8) * ldc + ncol]) = v1;
        }
    }
}

// ===========================================================================
// global atomic barrier (only used once at scan end for counter reset)
// ===========================================================================
__device__ __forceinline__ void grid_barrier_atomic()
{
    __syncthreads();
    if (threadIdx.x == 0) {
        unsigned gen;
        asm volatile("ld.acquire.gpu.global.u32 %0, [%1];"
                     : "=r"(gen) : "l"(&g_gen2));
        unsigned old;
        asm volatile("atom.acq_rel.gpu.global.add.u32 %0, [%1], 1;"
                     : "=r"(old) : "l"(&g_cnt2));
        if (old == gridDim.x - 1) {
            asm volatile("st.relaxed.gpu.global.u32 [%0], 0;"
                         :: "l"(&g_cnt2));
            asm volatile("red.release.gpu.global.add.u32 [%0], 1;"
                         :: "l"(&g_gen2));
        } else {
            unsigned cur;
            do {
                asm volatile("ld.acquire.gpu.global.u32 %0, [%1];"
                             : "=r"(cur) : "l"(&g_gen2));
            } while (cur == gen);
        }
    }
    __syncthreads();
}

// ===========================================================================
// Persistent recurrence: group semaphores (R15) + bf16x3/ldmatrix Phase A.
// h exchanged as packed bf16x2 hi/lo pair-words (double-buffered by t&1).
// ===========================================================================
__global__ __launch_bounds__(256) void rnn_scan_k(
    const float* __restrict__ h0, const float* __restrict__ Wi2h)
{
    __shared__ uint32_t sh_hi[64 * SSB];
    __shared__ uint32_t sh_lo[64 * SSB];

    const int tid = threadIdx.x;
    const int bid = blockIdx.x;
    const int wid = tid >> 5;
    const int lane = tid & 31;
    const int c   = bid >> 4;
    const int jt  = bid & 15;
    const int j0  = jt * JT;
    const int k0  = c * KC;

    const int mh = wid >> 2;
    const int nw = wid & 3;
    const int fr = lane >> 2;
    const int fc = lane & 3;

    const uint32_t u_hi = smem_u32(sh_hi);
    const uint32_t u_lo = smem_u32(sh_lo);
    const int a_row = mh * 32 + (lane & 15);
    const int a_colh = (lane >> 4) << 2;          // pair-words within k16 tile

    // preload W fragments as bf16 hi/lo (loop-invariant):
    // m16n8k16 B frag: b0 = k {2fc,2fc+1}, b1 = k {2fc+8,2fc+9}, col fr.
    uint32_t Wfh[2][8][2], Wfl[2][8][2];
#pragma unroll
    for (int nj = 0; nj < 2; nj++) {
        const int n = j0 + nw * 16 + nj * 8 + fr;
        const float* wr = &Wi2h[(size_t)n * (NIN + HID) + NIN + k0];
#pragma unroll
        for (int ks = 0; ks < 8; ks++) {
            const int kb = ks * 16;
            float w0 = wr[kb + 2 * fc],     w1 = wr[kb + 2 * fc + 1];
            float w8 = wr[kb + 2 * fc + 8], w9 = wr[kb + 2 * fc + 9];
            uint32_t h;
            h = pack_bf16_hi(w0, w1); Wfh[nj][ks][0] = h; Wfl[nj][ks][0] = pack_bf16_lo(h, w0, w1);
            h = pack_bf16_hi(w8, w9); Wfh[nj][ks][1] = h; Wfl[nj][ks][1] = pack_bf16_lo(h, w8, w9);
        }
    }

    // Phase B ownership: rows 4jt..4jt+3, cols k0..k0+127; 2 cols/thread
    const int pb_e   = 2 * tid;
    const int pb_b   = 4 * jt + (pb_e >> 7);
    const int pb_col = k0 + (pb_e & 127);
    unsigned* const b1_arr  = &g_b1[(jt >> 1) * 32];
    unsigned* const b1_wait = &g_b1[c * 32];
    unsigned* const b2_sem  = &g_b2[c * 32];

    for (int t = 0; t < T_STEPS; t++) {
        const int par = t & 1;

        // --- stage h(t-1) pair-words (64 rows x 64 words) ---
        if (t == 0) {
#pragma unroll
            for (int p = 0; p < 16; p++) {
                const int w = tid + p * 256;      // 0..4095
                const int b = w >> 6;
                const int col = w & 63;
                float2 v = *reinterpret_cast<const float2*>(
                    &h0[b * HID + k0 + 2 * col]);
                uint32_t h = pack_bf16_hi(v.x, v.y);
                sh_hi[b * SSB + col] = h;
                sh_lo[b * SSB + col] = pack_bf16_lo(h, v.x, v.y);
            }
        } else {
            const uint32_t* srchi = g_Hbfhi[(t - 1) & 1];
            const uint32_t* srclo = g_Hbflo[(t - 1) & 1];
#pragma unroll
            for (int p = 0; p < 4; p++) {
                const int q = tid + p * 256;      // 0..1023 uint4
                const int b = q >> 4;
                const int wg = (q & 15) * 4;
                const int go = b * (HID / 2) + (k0 >> 1) + wg;
                uint4 hv = __ldcg(reinterpret_cast<const uint4*>(&srchi[go]));
                uint4 lv = __ldcg(reinterpret_cast<const uint4*>(&srclo[go]));
                *reinterpret_cast<uint4*>(&sh_hi[b * SSB + wg]) = hv;
                *reinterpret_cast<uint4*>(&sh_lo[b * SSB + wg]) = lv;
            }
        }
        __syncthreads();

        // --- Phase A: bf16x3 mma over 8 k16 steps, ldmatrix frags ---
        float acc[2][2][4];
#pragma unroll
        for (int mi = 0; mi < 2; mi++)
#pragma unroll
            for (int nj = 0; nj < 2; nj++)
#pragma unroll
                for (int q = 0; q < 4; q++) acc[mi][nj][q] = 0.0f;

#pragma unroll
        for (int ks = 0; ks < 8; ks++) {
#pragma unroll
            for (int mi = 0; mi < 2; mi++) {
                const uint32_t off = (uint32_t)((a_row + mi * 16) * SSB
                                                + ks * 8 + a_colh) * 4u;
                uint32_t ah[4], al[4];
                ldsm_x4(ah[0], ah[1], ah[2], ah[3], u_hi + off);
                ldsm_x4(al[0], al[1], al[2], al[3], u_lo + off);
#pragma unroll
                for (int nj = 0; nj < 2; nj++) {
                    mma_bf16(acc[mi][nj][0], acc[mi][nj][1], acc[mi][nj][2], acc[mi][nj][3],
                             ah[0], ah[1], ah[2], ah[3],
                             Wfh[nj][ks][0], Wfh[nj][ks][1]);
                    mma_bf16(acc[mi][nj][0], acc[mi][nj][1], acc[mi][nj][2], acc[mi][nj][3],
                             ah[0], ah[1], ah[2], ah[3],
                             Wfl[nj][ks][0], Wfl[nj][ks][1]);
                    mma_bf16(acc[mi][nj][0], acc[mi][nj][1], acc[mi][nj][2], acc[mi][nj][3],
                             al[0], al[1], al[2], al[3],
                             Wfh[nj][ks][0], Wfh[nj][ks][1]);
                }
            }
        }

        // --- write partials into buffer par ---
        float* partbuf = g_part[par];
#pragma unroll
        for (int mi = 0; mi < 2; mi++) {
            const int b0 = mh * 32 + mi * 16 + fr;
#pragma unroll
            for (int nj = 0; nj < 2; nj++) {
                const int n = j0 + nw * 16 + nj * 8 + fc * 2;
                float2 v0, v1;
                v0.x = acc[mi][nj][0]; v0.y = acc[mi][nj][1];
                v1.x = acc[mi][nj][2]; v1.y = acc[mi][nj][3];
                __stcg(reinterpret_cast<float2*>(
                    &partbuf[(size_t)(c * BSZ + b0) * HID + n]), v0);
                __stcg(reinterpret_cast<float2*>(
                    &partbuf[(size_t)(c * BSZ + b0 + 8) * HID + n]), v1);
            }
        }

        // prefetch U before the wait
        const size_t u0 = ((size_t)t * BSZ + pb_b) * HID + pb_col;
        float2 uv = __ldcg(reinterpret_cast<const float2*>(&g_UH[u0]));

        // --- B1: arrive for consumer group (jt>>1); wait own 16 producers ---
        __syncthreads();
        if (tid == 0) {
            asm volatile("red.release.gpu.global.add.u32 [%0], 1;" :: "l"(b1_arr));
            const unsigned want = 16u * (unsigned)(t + 1);
            unsigned v;
            do {
                asm volatile("ld.acquire.gpu.global.u32 %0, [%1];"
                             : "=r"(v) : "l"(b1_wait));
            } while (v < want);
        }
        __syncthreads();

        // --- Phase B: reduce own 512 elems, tanh, write fp32 h + bf splits ---
        {
            float v0 = uv.x, v1 = uv.y;
#pragma unroll
            for (int cc = 0; cc < NC; cc++) {
                float2 p = __ldcg(reinterpret_cast<const float2*>(
                    &partbuf[(size_t)(cc * BSZ + pb_b) * HID + pb_col]));
                v0 += p.x;
                v1 += p.y;
            }
            v0 = tanhf(v0);
            v1 = tanhf(v1);
            float2 hw; hw.x = v0; hw.y = v1;
            __stcg(reinterpret_cast<float2*>(&g_UH[u0]), hw);   // h for GEMM3
            uint32_t hi2 = pack_bf16_hi(v0, v1);
            uint32_t lo2 = pack_bf16_lo(hi2, v0, v1);
            const int ho = pb_b * (HID / 2) + (pb_col >> 1);
            __stcg(&g_Hbfhi[par][ho], hi2);
            __stcg(&g_Hbflo[par][ho], lo2);
        }

        // --- B2: group-c internal barrier (h columns of group c ready) ---
        __syncthreads();
        if (tid == 0) {
            asm volatile("red.release.gpu.global.add.u32 [%0], 1;" :: "l"(b2_sem));
            const unsigned want = 16u * (unsigned)(t + 1);
            unsigned v;
            do {
                asm volatile("ld.acquire.gpu.global.u32 %0, [%1];"
                             : "=r"(v) : "l"(b2_sem));
            } while (v < want);
        }
        __syncthreads();
    }

    // reset semaphores for the next graph replay, behind a global barrier
    grid_barrier_atomic();
    if (jt == 0 && tid == 0) {
        asm volatile("st.relaxed.gpu.global.u32 [%0], 0;" :: "l"(&g_b1[c * 32]));
        asm volatile("st.relaxed.gpu.global.u32 [%0], 0;" :: "l"(&g_b2[c * 32]));
    }
}

// ===========================================================================
extern "C" void kernel_launch(void* const* d_in, const int* in_sizes, int n_in,
                              void* d_out, int out_size)
{
    (void)in_sizes; (void)n_in; (void)out_size;
    const float* x     = (const float*)d_in[0];
    const float* h0    = (const float*)d_in[1];
    const float* W_i2h = (const float*)d_in[2];
    const float* b_i2h = (const float*)d_in[3];
    const float* W_h2o = (const float*)d_in[4];
    const float* b_h2o = (const float*)d_in[5];
    float* out = (float*)d_out;

    float* uh = nullptr;
    cudaGetSymbolAddress((void**)&uh, g_UH);

    // 1) U = X @ Wx^T + b_i2h   (bf16x3 + ldmatrix)
    dim3 g1(HID / BN, (T_STEPS * BSZ) / BM);
    gemm_bf16_k<<<g1, 256>>>(x, NIN, W_i2h, NIN + HID, b_i2h, uh, HID, NIN);

    // 2) sequential recurrence (group semaphores + bf16x3 Phase A)
    rnn_scan_k<<<RNN_BLOCKS, 256>>>(h0, W_i2h);

    // 3) out = H @ W_h2o^T + b_h2o   (bf16x3 + ldmatrix)
    gemm_bf16_k<<<g1, 256>>>(uh, HID, W_h2o, HID, b_h2o, out, NOUT, HID);
}

// round 17
// speedup vs baseline: 2.4189x; 1.0337x over previous
#include <cuda_runtime.h>
#include <cstdint>

#define T_STEPS 512
#define BSZ     64
#define NIN     1024
#define HID     1024
#define NOUT    1024

// recurrence partition
#define NC       8
#define KC       128
#define JT       64
#define RNN_BLOCKS 128
#define SSB      68           // scan smem pair-word row stride (64 + 4 pad)

// scratch
__device__ float    g_UH[(size_t)T_STEPS * BSZ * HID];        // U (fp32)
__device__ uint32_t g_HThi[(size_t)T_STEPS * BSZ * HID / 2];  // bf16x2 hi of h_t
__device__ uint32_t g_HTlo[(size_t)T_STEPS * BSZ * HID / 2];  // bf16x2 lo of h_t
__device__ uint32_t g_xhi[(size_t)T_STEPS * BSZ * NIN / 2];
__device__ uint32_t g_xlo[(size_t)T_STEPS * BSZ * NIN / 2];
__device__ uint32_t g_Wxhi[HID * NIN / 2];
__device__ uint32_t g_Wxlo[HID * NIN / 2];
__device__ uint32_t g_Wohi[NOUT * HID / 2];
__device__ uint32_t g_Wolo[NOUT * HID / 2];
__device__ float    g_part[2][NC * BSZ * HID];                // k-split partials
// per-group semaphores + final barrier
__device__ unsigned g_b1[NC * 32];
__device__ unsigned g_b2[NC * 32];
__device__ unsigned g_cnt2;
__device__ unsigned g_gen2;

// ===========================================================================
// helpers
// ===========================================================================
__device__ __forceinline__ uint32_t smem_u32(const void* p) {
    uint32_t a;
    asm("{ .reg .u64 t; cvta.to.shared.u64 t, %1; cvt.u32.u64 %0, t; }"
        : "=r"(a) : "l"(p));
    return a;
}
__device__ __forceinline__ void cp_async16(uint32_t smem_addr, const void* gptr) {
    asm volatile("cp.async.cg.shared.global [%0], [%1], 16;"
                 :: "r"(smem_addr), "l"(gptr));
}
__device__ __forceinline__ void mma_bf16(
    float& d0, float& d1, float& d2, float& d3,
    uint32_t a0, uint32_t a1, uint32_t a2, uint32_t a3,
    uint32_t b0, uint32_t b1)
{
    asm volatile(
        "mma.sync.aligned.m16n8k16.row.col.f32.bf16.bf16.f32 "
        "{%0,%1,%2,%3}, {%4,%5,%6,%7}, {%8,%9}, {%0,%1,%2,%3};"
        : "+f"(d0), "+f"(d1), "+f"(d2), "+f"(d3)
        : "r"(a0), "r"(a1), "r"(a2), "r"(a3), "r"(b0), "r"(b1));
}
__device__ __forceinline__ uint32_t pack_bf16_hi(float f0, float f1) {
    uint32_t r;
    asm("cvt.rn.bf16x2.f32 %0, %1, %2;" : "=r"(r) : "f"(f1), "f"(f0));
    return r;
}
__device__ __forceinline__ uint32_t pack_bf16_lo(uint32_t hi2, float f0, float f1) {
    float h0 = __uint_as_float(hi2 << 16);
    float h1 = __uint_as_float(hi2 & 0xFFFF0000u);
    uint32_t r;
    asm("cvt.rn.bf16x2.f32 %0, %1, %2;" : "=r"(r) : "f"(f1 - h1), "f"(f0 - h0));
    return r;
}
__device__ __forceinline__ void ldsm_x4(
    uint32_t& r0, uint32_t& r1, uint32_t& r2, uint32_t& r3, uint32_t addr)
{
    asm volatile("ldmatrix.sync.aligned.m8n8.x4.shared.b16 {%0,%1,%2,%3}, [%4];"
                 : "=r"(r0), "=r"(r1), "=r"(r2), "=r"(r3) : "r"(addr));
}
__device__ __forceinline__ void ldsm_x2(
    uint32_t& r0, uint32_t& r1, uint32_t addr)
{
    asm volatile("ldmatrix.sync.aligned.m8n8.x2.shared.b16 {%0,%1}, [%2];"
                 : "=r"(r0), "=r"(r1) : "r"(addr));
}

// ===========================================================================
// prep: pack fp32 -> bf16x2 hi/lo word arrays (run once per launch)
// ===========================================================================
__global__ void pack_plain_k(const float* __restrict__ src,
                             uint32_t* __restrict__ hi, uint32_t* __restrict__ lo,
                             int n4)
{
    int i = blockIdx.x * blockDim.x + threadIdx.x;
    if (i >= n4) return;
    float4 v = reinterpret_cast<const float4*>(src)[i];
    uint32_t h0 = pack_bf16_hi(v.x, v.y);
    uint32_t h1 = pack_bf16_hi(v.z, v.w);
    uint2 hw, lw;
    hw.x = h0; hw.y = h1;
    lw.x = pack_bf16_lo(h0, v.x, v.y);
    lw.y = pack_bf16_lo(h1, v.z, v.w);
    reinterpret_cast<uint2*>(hi)[i] = hw;
    reinterpret_cast<uint2*>(lo)[i] = lw;
}

__global__ void pack_strided_k(const float* __restrict__ src, int srcld, int cols,
                               uint32_t* __restrict__ hi, uint32_t* __restrict__ lo,
                               int n4)
{
    int i = blockIdx.x * blockDim.x + threadIdx.x;
    if (i >= n4) return;
    int e = i * 4;
    int r = e / cols;
    int c0 = e - r * cols;
    float4 v = *reinterpret_cast<const float4*>(src + (size_t)r * srcld + c0);
    uint32_t h0 = pack_bf16_hi(v.x, v.y);
    uint32_t h1 = pack_bf16_hi(v.z, v.w);
    uint2 hw, lw;
    hw.x = h0; hw.y = h1;
    lw.x = pack_bf16_lo(h0, v.x, v.y);
    lw.y = pack_bf16_lo(h1, v.z, v.w);
    reinterpret_cast<uint2*>(hi)[i] = hw;
    reinterpret_cast<uint2*>(lo)[i] = lw;
}

// ===========================================================================
// bf16x3 GEMM, pre-packed operands, cp.async loads, ldmatrix frags.
// A/W given as bf16x2 hi/lo word arrays, Kw = K/2 words per row.
// CTA 128x128, 8 warps (2x4), warp tile 64x32; per iter K=16 (8 pair-words).
// ===========================================================================
#define BM 128
#define BN 128
#define SSTB 12
#define BTILE (BM * SSTB)

__global__ __launch_bounds__(256, 2) void gemm_bf16p_k(
    const uint32_t* __restrict__ Ahi_g, const uint32_t* __restrict__ Alo_g,
    const uint32_t* __restrict__ Whi_g, const uint32_t* __restrict__ Wlo_g,
    const float* __restrict__ bias,
    float* __restrict__ C, int ldc, int Kw)   // Kw = K/2 pair-words
{
    __shared__ uint32_t Ah[2][BTILE], Al[2][BTILE];
    __shared__ uint32_t Wh[2][BTILE], Wl[2][BTILE];

    const int tid = threadIdx.x;
    const int wid = tid >> 5;
    const int lane = tid & 31;
    const int m0 = blockIdx.y * BM;
    const int n0 = blockIdx.x * BN;

    const int warp_m = (wid >> 2) * 64;
    const int warp_n = (wid & 3) * 32;

    // loader: row = tid>>1, 4 pair-words (16B) at (tid&1)*4
    const int lrow = tid >> 1;
    const int wc   = (tid & 1) * 4;
    const uint32_t* gAh = Ahi_g + (size_t)(m0 + lrow) * Kw + wc;
    const uint32_t* gAl = Alo_g + (size_t)(m0 + lrow) * Kw + wc;
    const uint32_t* gWh = Whi_g + (size_t)(n0 + lrow) * Kw + wc;
    const uint32_t* gWl = Wlo_g + (size_t)(n0 + lrow) * Kw + wc;

    const uint32_t uAh = smem_u32(&Ah[0][0]);
    const uint32_t uAl = smem_u32(&Al[0][0]);
    const uint32_t uWh = smem_u32(&Wh[0][0]);
    const uint32_t uWl = smem_u32(&Wl[0][0]);
    const uint32_t soff = (uint32_t)(lrow * SSTB + wc) * 4u;

    const int a_row = warp_m + (lane & 15);
    const int a_col = (lane >> 4) << 2;
    const int b_row = warp_n + (lane & 7);
    const int b_col = ((lane >> 3) & 1) << 2;

    const int NK = Kw / 8;   // iters of 8 pair-words (K=16)

    // prefetch tile 0
    {
        cp_async16(uAh + soff, gAh);
        cp_async16(uAl + soff, gAl);
        cp_async16(uWh + soff, gWh);
        cp_async16(uWl + soff, gWl);
        asm volatile("cp.async.commit_group;");
    }

    float acc[4][4][4];
#pragma unroll
    for (int i = 0; i < 4; i++)
#pragma unroll
        for (int j = 0; j < 4; j++)
#pragma unroll
            for (int q = 0; q < 4; q++) acc[i][j][q] = 0.0f;

    const int fr = lane >> 2;
    const int fc = lane & 3;

    for (int it = 0; it < NK; it++) {
        const int buf = it & 1;
        const uint32_t bufo = (uint32_t)buf * (BTILE * 4);

        if (it + 1 < NK) {
            const uint32_t d = (uint32_t)((it + 1) & 1) * (BTILE * 4);
            const int ko = (it + 1) * 8;
            cp_async16(uAh + d + soff, gAh + ko);
            cp_async16(uAl + d + soff, gAl + ko);
            cp_async16(uWh + d + soff, gWh + ko);
            cp_async16(uWl + d + soff, gWl + ko);
            asm volatile("cp.async.commit_group;");
            asm volatile("cp.async.wait_group 1;");
        } else {
            asm volatile("cp.async.wait_group 0;");
        }
        __syncthreads();

        uint32_t bh[4][2], bl[4][2];
#pragma unroll
        for (int j = 0; j < 4; j++) {
            const uint32_t off = (uint32_t)((b_row + j * 8) * SSTB + b_col) * 4u + bufo;
            ldsm_x2(bh[j][0], bh[j][1], uWh + off);
            ldsm_x2(bl[j][0], bl[j][1], uWl + off);
        }

#pragma unroll
        for (int i = 0; i < 4; i++) {
            const uint32_t off = (uint32_t)((a_row + i * 16) * SSTB + a_col) * 4u + bufo;
            uint32_t ah[4], al[4];
            ldsm_x4(ah[0], ah[1], ah[2], ah[3], uAh + off);
            ldsm_x4(al[0], al[1], al[2], al[3], uAl + off);

#pragma unroll
            for (int j = 0; j < 4; j++) {
                mma_bf16(acc[i][j][0], acc[i][j][1], acc[i][j][2], acc[i][j][3],
                         ah[0], ah[1], ah[2], ah[3], bh[j][0], bh[j][1]);
                mma_bf16(acc[i][j][0], acc[i][j][1], acc[i][j][2], acc[i][j][3],
                         ah[0], ah[1], ah[2], ah[3], bl[j][0], bl[j][1]);
                mma_bf16(acc[i][j][0], acc[i][j][1], acc[i][j][2], acc[i][j][3],
                         al[0], al[1], al[2], al[3], bh[j][0], bh[j][1]);
            }
        }
        __syncthreads();
    }

#pragma unroll
    for (int j = 0; j < 4; j++) {
        const int ncol = n0 + warp_n + j * 8 + fc * 2;
        const float2 bv = *reinterpret_cast<const float2*>(&bias[ncol]);
#pragma unroll
        for (int i = 0; i < 4; i++) {
            const int r0 = m0 + warp_m + i * 16 + fr;
            float2 v0, v1;
            v0.x = acc[i][j][0] + bv.x; v0.y = acc[i][j][1] + bv.y;
            v1.x = acc[i][j][2] + bv.x; v1.y = acc[i][j][3] + bv.y;
            *reinterpret_cast<float2*>(&C[(size_t)r0 * ldc + ncol])       = v0;
            *reinterpret_cast<float2*>(&C[(size_t)(r0 + 8) * ldc + ncol]) = v1;
        }
    }
}

// ===========================================================================
// global atomic barrier (scan-end reset only)
// ===========================================================================
__device__ __forceinline__ void grid_barrier_atomic()
{
    __syncthreads();
    if (threadIdx.x == 0) {
        unsigned gen;
        asm volatile("ld.acquire.gpu.global.u32 %0, [%1];"
                     : "=r"(gen) : "l"(&g_gen2));
        unsigned old;
        asm volatile("atom.acq_rel.gpu.global.add.u32 %0, [%1], 1;"
                     : "=r"(old) : "l"(&g_cnt2));
        if (old == gridDim.x - 1) {
            asm volatile("st.relaxed.gpu.global.u32 [%0], 0;"
                         :: "l"(&g_cnt2));
            asm volatile("red.release.gpu.global.add.u32 [%0], 1;"
                         :: "l"(&g_gen2));
        } else {
            unsigned cur;
            do {
                asm volatile("ld.acquire.gpu.global.u32 %0, [%1];"
                             : "=r"(cur) : "l"(&g_gen2));
            } while (cur == gen);
        }
    }
    __syncthreads();
}

// ===========================================================================
// Persistent recurrence (R16 structure): group semaphores + bf16x3 Phase A.
// h stored per-t as packed bf16x2 hi/lo (consumed directly by GEMM3).
// ===========================================================================
__global__ __launch_bounds__(256) void rnn_scan_k(
    const float* __restrict__ h0, const float* __restrict__ Wi2h)
{
    __shared__ uint32_t sh_hi[64 * SSB];
    __shared__ uint32_t sh_lo[64 * SSB];

    const int tid = threadIdx.x;
    const int bid = blockIdx.x;
    const int wid = tid >> 5;
    const int lane = tid & 31;
    const int c   = bid >> 4;
    const int jt  = bid & 15;
    const int j0  = jt * JT;
    const int k0  = c * KC;

    const int mh = wid >> 2;
    const int nw = wid & 3;
    const int fr = lane >> 2;
    const int fc = lane & 3;

    const uint32_t u_hi = smem_u32(sh_hi);
    const uint32_t u_lo = smem_u32(sh_lo);
    const int a_row = mh * 32 + (lane & 15);
    const int a_colh = (lane >> 4) << 2;

    // preload W fragments as bf16 hi/lo (loop-invariant)
    uint32_t Wfh[2][8][2], Wfl[2][8][2];
#pragma unroll
    for (int nj = 0; nj < 2; nj++) {
        const int n = j0 + nw * 16 + nj * 8 + fr;
        const float* wr = &Wi2h[(size_t)n * (NIN + HID) + NIN + k0];
#pragma unroll
        for (int ks = 0; ks < 8; ks++) {
            const int kb = ks * 16;
            float w0 = wr[kb + 2 * fc],     w1 = wr[kb + 2 * fc + 1];
            float w8 = wr[kb + 2 * fc + 8], w9 = wr[kb + 2 * fc + 9];
            uint32_t h;
            h = pack_bf16_hi(w0, w1); Wfh[nj][ks][0] = h; Wfl[nj][ks][0] = pack_bf16_lo(h, w0, w1);
            h = pack_bf16_hi(w8, w9); Wfh[nj][ks][1] = h; Wfl[nj][ks][1] = pack_bf16_lo(h, w8, w9);
        }
    }

    // Phase B ownership: rows 4jt..4jt+3, cols k0..k0+127; 2 cols/thread
    const int pb_e   = 2 * tid;
    const int pb_b   = 4 * jt + (pb_e >> 7);
    const int pb_col = k0 + (pb_e & 127);
    unsigned* const b1_arr  = &g_b1[(jt >> 1) * 32];
    unsigned* const b1_wait = &g_b1[c * 32];
    unsigned* const b2_sem  = &g_b2[c * 32];

    for (int t = 0; t < T_STEPS; t++) {
        const int par = t & 1;

        // --- stage h(t-1) pair-words ---
        if (t == 0) {
#pragma unroll
            for (int p = 0; p < 16; p++) {
                const int w = tid + p * 256;
                const int b = w >> 6;
                const int col = w & 63;
                float2 v = *reinterpret_cast<const float2*>(
                    &h0[b * HID + k0 + 2 * col]);
                uint32_t h = pack_bf16_hi(v.x, v.y);
                sh_hi[b * SSB + col] = h;
                sh_lo[b * SSB + col] = pack_bf16_lo(h, v.x, v.y);
            }
        } else {
            const uint32_t* srchi = g_HThi + (size_t)(t - 1) * (BSZ * HID / 2);
            const uint32_t* srclo = g_HTlo + (size_t)(t - 1) * (BSZ * HID / 2);
#pragma unroll
            for (int p = 0; p < 4; p++) {
                const int q = tid + p * 256;
                const int b = q >> 4;
                const int wg = (q & 15) * 4;
                const int go = b * (HID / 2) + (k0 >> 1) + wg;
                uint4 hv = __ldcg(reinterpret_cast<const uint4*>(&srchi[go]));
                uint4 lv = __ldcg(reinterpret_cast<const uint4*>(&srclo[go]));
                *reinterpret_cast<uint4*>(&sh_hi[b * SSB + wg]) = hv;
                *reinterpret_cast<uint4*>(&sh_lo[b * SSB + wg]) = lv;
            }
        }
        __syncthreads();

        // --- Phase A: bf16x3 mma over 8 k16 steps ---
        float acc[2][2][4];
#pragma unroll
        for (int mi = 0; mi < 2; mi++)
#pragma unroll
            for (int nj = 0; nj < 2; nj++)
#pragma unroll
                for (int q = 0; q < 4; q++) acc[mi][nj][q] = 0.0f;

#pragma unroll
        for (int ks = 0; ks < 8; ks++) {
#pragma unroll
            for (int mi = 0; mi < 2; mi++) {
                const uint32_t off = (uint32_t)((a_row + mi * 16) * SSB
                                                + ks * 8 + a_colh) * 4u;
                uint32_t ah[4], al[4];
                ldsm_x4(ah[0], ah[1], ah[2], ah[3], u_hi + off);
                ldsm_x4(al[0], al[1], al[2], al[3], u_lo + off);
#pragma unroll
                for (int nj = 0; nj < 2; nj++) {
                    mma_bf16(acc[mi][nj][0], acc[mi][nj][1], acc[mi][nj][2], acc[mi][nj][3],
                             ah[0], ah[1], ah[2], ah[3],
                             Wfh[nj][ks][0], Wfh[nj][ks][1]);
                    mma_bf16(acc[mi][nj][0], acc[mi][nj][1], acc[mi][nj][2], acc[mi][nj][3],
                             ah[0], ah[1], ah[2], ah[3],
                             Wfl[nj][ks][0], Wfl[nj][ks][1]);
                    mma_bf16(acc[mi][nj][0], acc[mi][nj][1], acc[mi][nj][2], acc[mi][nj][3],
                             al[0], al[1], al[2], al[3],
                             Wfh[nj][ks][0], Wfh[nj][ks][1]);
                }
            }
        }

        // --- write partials into buffer par ---
        float* partbuf = g_part[par];
#pragma unroll
        for (int mi = 0; mi < 2; mi++) {
            const int b0 = mh * 32 + mi * 16 + fr;
#pragma unroll
            for (int nj = 0; nj < 2; nj++) {
                const int n = j0 + nw * 16 + nj * 8 + fc * 2;
                float2 v0, v1;
                v0.x = acc[mi][nj][0]; v0.y = acc[mi][nj][1];
                v1.x = acc[mi][nj][2]; v1.y = acc[mi][nj][3];
                __stcg(reinterpret_cast<float2*>(
                    &partbuf[(size_t)(c * BSZ + b0) * HID + n]), v0);
                __stcg(reinterpret_cast<float2*>(
                    &partbuf[(size_t)(c * BSZ + b0 + 8) * HID + n]), v1);
            }
        }

        // prefetch U before the wait
        const size_t u0 = ((size_t)t * BSZ + pb_b) * HID + pb_col;
        float2 uv = __ldcg(reinterpret_cast<const float2*>(&g_UH[u0]));

        // --- B1 ---
        __syncthreads();
        if (tid == 0) {
            asm volatile("red.release.gpu.global.add.u32 [%0], 1;" :: "l"(b1_arr));
            const unsigned want = 16u * (unsigned)(t + 1);
            unsigned v;
            do {
                asm volatile("ld.acquire.gpu.global.u32 %0, [%1];"
                             : "=r"(v) : "l"(b1_wait));
            } while (v < want);
        }
        __syncthreads();

        // --- Phase B: reduce, tanh, store packed bf16 h(t) per-t ---
        {
            float v0 = uv.x, v1 = uv.y;
#pragma unroll
            for (int cc = 0; cc < NC; cc++) {
                float2 p = __ldcg(reinterpret_cast<const float2*>(
                    &partbuf[(size_t)(cc * BSZ + pb_b) * HID + pb_col]));
                v0 += p.x;
                v1 += p.y;
            }
            v0 = tanhf(v0);
            v1 = tanhf(v1);
            uint32_t hi2 = pack_bf16_hi(v0, v1);
            uint32_t lo2 = pack_bf16_lo(hi2, v0, v1);
            const size_t ho = (size_t)t * (BSZ * HID / 2)
                            + pb_b * (HID / 2) + (pb_col >> 1);
            __stcg(&g_HThi[ho], hi2);
            __stcg(&g_HTlo[ho], lo2);
        }

        // --- B2 ---
        __syncthreads();
        if (tid == 0) {
            asm volatile("red.release.gpu.global.add.u32 [%0], 1;" :: "l"(b2_sem));
            const unsigned want = 16u * (unsigned)(t + 1);
            unsigned v;
            do {
                asm volatile("ld.acquire.gpu.global.u32 %0, [%1];"
                             : "=r"(v) : "l"(b2_sem));
            } while (v < want);
        }
        __syncthreads();
    }

    // reset semaphores behind a global barrier
    grid_barrier_atomic();
    if (jt == 0 && tid == 0) {
        asm volatile("st.relaxed.gpu.global.u32 [%0], 0;" :: "l"(&g_b1[c * 32]));
        asm volatile("st.relaxed.gpu.global.u32 [%0], 0;" :: "l"(&g_b2[c * 32]));
    }
}

// ===========================================================================
extern "C" void kernel_launch(void* const* d_in, const int* in_sizes, int n_in,
                              void* d_out, int out_size)
{
    (void)in_sizes; (void)n_in; (void)out_size;
    const float* x     = (const float*)d_in[0];
    const float* h0    = (const float*)d_in[1];
    const float* W_i2h = (const float*)d_in[2];
    const float* b_i2h = (const float*)d_in[3];
    const float* W_h2o = (const float*)d_in[4];
    const float* b_h2o = (const float*)d_in[5];
    float* out = (float*)d_out;

    float *uh;
    uint32_t *xhi, *xlo, *wxhi, *wxlo, *wohi, *wolo, *hthi, *htlo;
    cudaGetSymbolAddress((void**)&uh,   g_UH);
    cudaGetSymbolAddress((void**)&xhi,  g_xhi);
    cudaGetSymbolAddress((void**)&xlo,  g_xlo);
    cudaGetSymbolAddress((void**)&wxhi, g_Wxhi);
    cudaGetSymbolAddress((void**)&wxlo, g_Wxlo);
    cudaGetSymbolAddress((void**)&wohi, g_Wohi);
    cudaGetSymbolAddress((void**)&wolo, g_Wolo);
    cudaGetSymbolAddress((void**)&hthi, g_HThi);
    cudaGetSymbolAddress((void**)&htlo, g_HTlo);

    // 0) prep: pack x, Wx, Wo into bf16x2 hi/lo word arrays
    {
        int n4x = (T_STEPS * BSZ * NIN) / 4;
        pack_plain_k<<<(n4x + 255) / 256, 256>>>(x, xhi, xlo, n4x);
        int n4w = (HID * NIN) / 4;
        pack_strided_k<<<(n4w + 255) / 256, 256>>>(W_i2h, NIN + HID, NIN,
                                                   wxhi, wxlo, n4w);
        int n4o = (NOUT * HID) / 4;
        pack_plain_k<<<(n4o + 255) / 256, 256>>>(W_h2o, wohi, wolo, n4o);
    }

    // 1) U = X @ Wx^T + b_i2h
    dim3 g1(HID / BN, (T_STEPS * BSZ) / BM);
    gemm_bf16p_k<<<g1, 256>>>(xhi, xlo, wxhi, wxlo, b_i2h, uh, HID, NIN / 2);

    // 2) sequential recurrence (produces packed h per-t)
    rnn_scan_k<<<RNN_BLOCKS, 256>>>(h0, W_i2h);

    // 3) out = H @ Wo^T + b_h2o  (A = scan's packed h, no prep needed)
    gemm_bf16p_k<<<g1, 256>>>(hthi, htlo, wohi, wolo, b_h2o, out, NOUT, HID / 2);
}